// round 1
// baseline (speedup 1.0000x reference)
#include <cuda_runtime.h>

#define M_ROWS 8192   // B*S
#define D      1024
#define S_LEN  256
#define NH     16
#define DK     64
#define BATCH  32

// ---------------- scratch (static device globals; no allocation) ----------------
__device__ float g_q[M_ROWS * D];
__device__ float g_k[M_ROWS * D];
__device__ float g_v[M_ROWS * D];
__device__ float g_attn[M_ROWS * D];
__device__ float g_y[M_ROWS * D];
__device__ float g_awp[(size_t)BATCH * NH * S_LEN * S_LEN];  // per-head plain softmax
__device__ float g_div[BATCH * 64 * 64];

// ---------------- div bias: div = 1 - softmax(pf @ pf^T) ----------------
__global__ void div_kernel(const float* __restrict__ pf, float* __restrict__ divb) {
    __shared__ float p[64 * 129];
    const int b = blockIdx.x;
    const int tid = threadIdx.x;  // 64 threads
    for (int idx = tid; idx < 64 * 128; idx += 64) {
        int r = idx >> 7, f = idx & 127;
        p[r * 129 + f] = pf[(size_t)b * 64 * 128 + idx];
    }
    __syncthreads();
    float simr[64];
    float mx = -1e30f;
    for (int q = 0; q < 64; ++q) {
        float dsum = 0.f;
        #pragma unroll 8
        for (int f = 0; f < 128; ++f)
            dsum = fmaf(p[tid * 129 + f], p[q * 129 + f], dsum);
        simr[q] = dsum;
        mx = fmaxf(mx, dsum);
    }
    float sum = 0.f;
    for (int q = 0; q < 64; ++q) { simr[q] = __expf(simr[q] - mx); sum += simr[q]; }
    float inv = 1.f / sum;
    for (int q = 0; q < 64; ++q)
        divb[((size_t)b * 64 + tid) * 64 + q] = 1.f - simr[q] * inv;
}

// ---------------- fp32 SGEMM: C[m,n] = sum_k A[m,k] * W[n,k] (+bias, epilogues) --
// A: M_ROWS x D row-major, W: D x D row-major (output-feature rows)
// epi==0: scatter to (b,h,s,k) layout with scale   epi==1: plain row-major + bias
__global__ void __launch_bounds__(256) gemm_nt(const float* __restrict__ A,
                                               const float* __restrict__ W,
                                               const float* __restrict__ bias,
                                               float* __restrict__ C,
                                               float scale, int epi) {
    __shared__ float As[8][132];
    __shared__ float Bs[8][132];
    const int tid = threadIdx.x;
    const int m0 = blockIdx.y * 128, n0 = blockIdx.x * 128;
    const int tx = tid & 15, ty = tid >> 4;
    const int lrow = tid >> 1;
    const int lk = (tid & 1) << 2;
    const float* Ap = A + (size_t)(m0 + lrow) * D + lk;
    const float* Wp = W + (size_t)(n0 + lrow) * D + lk;

    float acc[8][8];
    #pragma unroll
    for (int i = 0; i < 8; ++i)
        #pragma unroll
        for (int j = 0; j < 8; ++j) acc[i][j] = 0.f;

    for (int k0 = 0; k0 < D; k0 += 8) {
        float4 a4 = *(const float4*)(Ap + k0);
        float4 w4 = *(const float4*)(Wp + k0);
        __syncthreads();
        As[lk + 0][lrow] = a4.x; As[lk + 1][lrow] = a4.y;
        As[lk + 2][lrow] = a4.z; As[lk + 3][lrow] = a4.w;
        Bs[lk + 0][lrow] = w4.x; Bs[lk + 1][lrow] = w4.y;
        Bs[lk + 2][lrow] = w4.z; Bs[lk + 3][lrow] = w4.w;
        __syncthreads();
        #pragma unroll
        for (int k = 0; k < 8; ++k) {
            float ar[8], br[8];
            *(float4*)(ar)     = *(const float4*)(&As[k][ty * 8]);
            *(float4*)(ar + 4) = *(const float4*)(&As[k][ty * 8 + 4]);
            *(float4*)(br)     = *(const float4*)(&Bs[k][tx * 8]);
            *(float4*)(br + 4) = *(const float4*)(&Bs[k][tx * 8 + 4]);
            #pragma unroll
            for (int i = 0; i < 8; ++i)
                #pragma unroll
                for (int j = 0; j < 8; ++j)
                    acc[i][j] = fmaf(ar[i], br[j], acc[i][j]);
        }
    }

    if (epi == 0) {
        // scatter into (b, h, s, k) layout: dst[((b*16+h)*256+s)*64+k]
        #pragma unroll
        for (int i = 0; i < 8; ++i) {
            int m = m0 + ty * 8 + i;
            int b = m >> 8, s = m & 255;
            #pragma unroll
            for (int j = 0; j < 8; ++j) {
                int nn = n0 + tx * 8 + j;
                int h = nn >> 6, kk = nn & 63;
                C[(((size_t)(b * NH + h) * S_LEN + s) << 6) + kk] =
                    (acc[i][j] + bias[nn]) * scale;
            }
        }
    } else {
        #pragma unroll
        for (int i = 0; i < 8; ++i) {
            int m = m0 + ty * 8 + i;
            #pragma unroll
            for (int j = 0; j < 8; ++j) {
                int nn = n0 + tx * 8 + j;
                C[(size_t)m * D + nn] = acc[i][j] + bias[nn];
            }
        }
    }
}

// ---------------- fused attention per (b, head) ----------------
// smem: K transposed (padded), V, Q; computes biased softmax -> AV (scrambled
// "torch-bug" layout into g_attn) and plain softmax -> g_awp.
__global__ void __launch_bounds__(256) attn_kernel(const float* __restrict__ Q,
                                                   const float* __restrict__ K,
                                                   const float* __restrict__ V,
                                                   const float* __restrict__ Div,
                                                   float* __restrict__ attnb,
                                                   float* __restrict__ awp) {
    extern __shared__ float sm[];
    float* Ks  = sm;                    // [64][257] transposed, padded
    float* Vs  = Ks + 64 * 257;         // [256][64]
    float* Qs  = Vs + 256 * 64;         // [256][64]
    float* aw  = Qs + 256 * 64;         // [256]
    float* avP = aw + 256;              // [4][64]
    float* red = avP + 256;             // [32]

    const int tid = threadIdx.x;
    const int bh = blockIdx.x;          // b*16 + n
    const int b = bh >> 4, n = bh & 15;
    const size_t base = (size_t)bh * (S_LEN * DK);

    for (int idx = tid; idx < S_LEN * DK; idx += 256) {
        int t = idx >> 6, i = idx & 63;
        Ks[i * 257 + t] = K[base + idx];
        Vs[idx] = V[base + idx];
        Qs[idx] = Q[base + idx];
    }
    __syncthreads();

    const int t = tid;
    const int lane = tid & 31, wrp = tid >> 5;
    float* awp_base = awp + (size_t)bh * (S_LEN * S_LEN);

    for (int s = 0; s < S_LEN; ++s) {
        // scores (Q already pre-scaled by 1/sqrt(dk))
        float sc = 0.f;
        const float* q = Qs + s * DK;
        #pragma unroll
        for (int i = 0; i < DK; ++i)
            sc = fmaf(q[i], Ks[i * 257 + t], sc);
        float scb = sc;
        if (s < 64 && t < 64)
            scb += 0.1f * Div[((b * 64 + s) << 6) + t];

        // block max for both variants
        float m1 = sc, m2 = scb;
        #pragma unroll
        for (int o = 16; o; o >>= 1) {
            m1 = fmaxf(m1, __shfl_xor_sync(0xffffffffu, m1, o));
            m2 = fmaxf(m2, __shfl_xor_sync(0xffffffffu, m2, o));
        }
        if (lane == 0) { red[wrp] = m1; red[8 + wrp] = m2; }
        __syncthreads();
        m1 = red[0]; m2 = red[8];
        #pragma unroll
        for (int w = 1; w < 8; ++w) {
            m1 = fmaxf(m1, red[w]); m2 = fmaxf(m2, red[8 + w]);
        }

        float ep = __expf(sc  - m1);
        float eb = __expf(scb - m2);
        aw[t] = eb;

        // block sums (disjoint red slots; no extra barrier needed before write)
        float s1 = ep, s2 = eb;
        #pragma unroll
        for (int o = 16; o; o >>= 1) {
            s1 += __shfl_xor_sync(0xffffffffu, s1, o);
            s2 += __shfl_xor_sync(0xffffffffu, s2, o);
        }
        if (lane == 0) { red[16 + wrp] = s1; red[24 + wrp] = s2; }
        __syncthreads();
        s1 = 0.f; s2 = 0.f;
        #pragma unroll
        for (int w = 0; w < 8; ++w) { s1 += red[16 + w]; s2 += red[24 + w]; }

        // plain softmax -> per-head aw buffer (pre-bias, for head-mean output)
        awp_base[s * S_LEN + t] = ep * (1.f / s1);

        // AV with biased weights: 4 groups of 64 keys, 64 dims each
        const int g = tid >> 6, kk = tid & 63;
        float part = 0.f;
        const float* vg = Vs + g * 64 * 64;
        const float* ag = aw + g * 64;
        #pragma unroll 8
        for (int j = 0; j < 64; ++j)
            part = fmaf(ag[j], vg[j * 64 + kk], part);
        avP[g * 64 + kk] = part;
        __syncthreads();
        if (tid < 64) {
            float o = (avP[tid] + avP[64 + tid] + avP[128 + tid] + avP[192 + tid])
                      * (1.f / s2);
            // faithful torch reshape scramble:
            int hi = b >> 4;
            int bp = 2 * n + hi;
            int sp = ((b & 15) << 4) | (s >> 4);
            int c  = ((s & 15) << 6) | tid;
            attnb[((size_t)bp * S_LEN + sp) * D + c] = o;
        }
        __syncthreads();
    }
}

// ---------------- mean over heads of plain attention weights ----------------
__global__ void awmean_kernel(const float* __restrict__ awp, float* __restrict__ out) {
    int idx = blockIdx.x * blockDim.x + threadIdx.x;  // < 32*256*256
    int b = idx >> 16;
    int r = idx & 65535;
    const float* p = awp + (size_t)b * NH * 65536 + r;
    float sum = 0.f;
    #pragma unroll
    for (int h = 0; h < NH; ++h) sum += p[(size_t)h * 65536];
    out[idx] = sum * (1.f / NH);
}

// ---------------- residual + layernorm ----------------
__global__ void __launch_bounds__(256) ln_kernel(const float* __restrict__ Y,
                                                 const float* __restrict__ X,
                                                 const float* __restrict__ G,
                                                 const float* __restrict__ Bb,
                                                 float* __restrict__ out) {
    __shared__ float red[8];
    const int row = blockIdx.x, tid = threadIdx.x;
    const int lane = tid & 31, w = tid >> 5;
    const size_t off = (size_t)row * D + tid * 4;
    float4 v  = *(const float4*)(Y + off);
    float4 xx = *(const float4*)(X + off);
    v.x += xx.x; v.y += xx.y; v.z += xx.z; v.w += xx.w;

    float s = v.x + v.y + v.z + v.w;
    #pragma unroll
    for (int o = 16; o; o >>= 1) s += __shfl_xor_sync(0xffffffffu, s, o);
    if (lane == 0) red[w] = s;
    __syncthreads();
    float tot = 0.f;
    #pragma unroll
    for (int i = 0; i < 8; ++i) tot += red[i];
    float mu = tot * (1.f / 1024.f);
    __syncthreads();

    float d0 = v.x - mu, d1 = v.y - mu, d2 = v.z - mu, d3 = v.w - mu;
    float sq = d0 * d0 + d1 * d1 + d2 * d2 + d3 * d3;
    #pragma unroll
    for (int o = 16; o; o >>= 1) sq += __shfl_xor_sync(0xffffffffu, sq, o);
    if (lane == 0) red[w] = sq;
    __syncthreads();
    float vtot = 0.f;
    #pragma unroll
    for (int i = 0; i < 8; ++i) vtot += red[i];
    float rstd = rsqrtf(vtot * (1.f / 1024.f) + 1e-5f);

    float4 g4 = *(const float4*)(G  + tid * 4);
    float4 b4 = *(const float4*)(Bb + tid * 4);
    float4 o;
    o.x = d0 * rstd * g4.x + b4.x;
    o.y = d1 * rstd * g4.y + b4.y;
    o.z = d2 * rstd * g4.z + b4.z;
    o.w = d3 * rstd * g4.w + b4.w;
    *(float4*)(out + off) = o;
}

// ---------------- launcher ----------------
extern "C" void kernel_launch(void* const* d_in, const int* in_sizes, int n_in,
                              void* d_out, int out_size) {
    const float* x   = (const float*)d_in[0];
    const float* pf  = (const float*)d_in[1];
    const float* wq  = (const float*)d_in[2];
    const float* bq  = (const float*)d_in[3];
    const float* wk  = (const float*)d_in[4];
    const float* bk  = (const float*)d_in[5];
    const float* wv  = (const float*)d_in[6];
    const float* bv  = (const float*)d_in[7];
    const float* wo  = (const float*)d_in[8];
    const float* bo  = (const float*)d_in[9];
    const float* lng = (const float*)d_in[10];
    const float* lnb = (const float*)d_in[11];

    float* out    = (float*)d_out;
    float* out_aw = out + (size_t)M_ROWS * D;

    float *qp, *kp, *vp, *ap, *yp, *awpp, *divp;
    cudaGetSymbolAddress((void**)&qp,   g_q);
    cudaGetSymbolAddress((void**)&kp,   g_k);
    cudaGetSymbolAddress((void**)&vp,   g_v);
    cudaGetSymbolAddress((void**)&ap,   g_attn);
    cudaGetSymbolAddress((void**)&yp,   g_y);
    cudaGetSymbolAddress((void**)&awpp, g_awp);
    cudaGetSymbolAddress((void**)&divp, g_div);

    div_kernel<<<BATCH, 64>>>(pf, divp);

    dim3 gg(D / 128, M_ROWS / 128);
    gemm_nt<<<gg, 256>>>(x, wq, bq, qp, 0.125f, 0);  // fold 1/sqrt(dk) into Q
    gemm_nt<<<gg, 256>>>(x, wk, bk, kp, 1.0f, 0);
    gemm_nt<<<gg, 256>>>(x, wv, bv, vp, 1.0f, 0);

    const size_t ATTN_SMEM = (size_t)(64 * 257 + 2 * 256 * 64 + 256 + 256 + 32) * sizeof(float);
    cudaFuncSetAttribute(attn_kernel, cudaFuncAttributeMaxDynamicSharedMemorySize,
                         (int)ATTN_SMEM);
    attn_kernel<<<BATCH * NH, 256, ATTN_SMEM>>>(qp, kp, vp, divp, ap, awpp);

    awmean_kernel<<<(BATCH * S_LEN * S_LEN) / 1024, 1024>>>(awpp, out_aw);

    gemm_nt<<<gg, 256>>>(ap, wo, bo, yp, 1.0f, 1);
    ln_kernel<<<M_ROWS, 256>>>(yp, x, lng, lnb, out);
}

// round 2
// speedup vs baseline: 1.2932x; 1.2932x over previous
#include <cuda_runtime.h>

typedef unsigned long long ull;

#define M_ROWS 8192   // B*S
#define D      1024
#define S_LEN  256
#define NH     16
#define DK     64
#define BATCH  32
#define PS     260    // P tile row stride (floats)

// ---------------- scratch ----------------
__device__ float g_q[M_ROWS * D];
__device__ float g_k[M_ROWS * D];
__device__ float g_v[M_ROWS * D];
__device__ float g_attn[M_ROWS * D];
__device__ float g_y[M_ROWS * D];
__device__ float g_awp[(size_t)BATCH * NH * S_LEN * S_LEN];
__device__ float g_div[BATCH * 64 * 64];

// ---------------- f32x2 helpers ----------------
__device__ __forceinline__ ull dup2(float x) {
    ull r; asm("mov.b64 %0,{%1,%1};" : "=l"(r) : "f"(x)); return r;
}
__device__ __forceinline__ void fma2(ull& d, ull a, ull b) {
    asm("fma.rn.f32x2 %0,%1,%2,%0;" : "+l"(d) : "l"(a), "l"(b));
}
__device__ __forceinline__ float2 unp2(ull v) {
    float2 f; asm("mov.b64 {%0,%1},%2;" : "=f"(f.x), "=f"(f.y) : "l"(v)); return f;
}
__device__ __forceinline__ float rmax16(float v) {
    #pragma unroll
    for (int o = 8; o; o >>= 1) v = fmaxf(v, __shfl_xor_sync(0xffffffffu, v, o));
    return v;
}
__device__ __forceinline__ float rsum16(float v) {
    #pragma unroll
    for (int o = 8; o; o >>= 1) v += __shfl_xor_sync(0xffffffffu, v, o);
    return v;
}

// ---------------- div bias: div = (1 - softmax(pf @ pf^T)) * 0.1 pre-scaled later
__global__ void div_kernel(const float* __restrict__ pf, float* __restrict__ divb) {
    __shared__ float p[64 * 129];
    const int b = blockIdx.x;
    const int tid = threadIdx.x;  // 64 threads
    for (int idx = tid; idx < 64 * 128; idx += 64) {
        int r = idx >> 7, f = idx & 127;
        p[r * 129 + f] = pf[(size_t)b * 64 * 128 + idx];
    }
    __syncthreads();
    float simr[64];
    float mx = -1e30f;
    for (int q = 0; q < 64; ++q) {
        float dsum = 0.f;
        #pragma unroll 8
        for (int f = 0; f < 128; ++f)
            dsum = fmaf(p[tid * 129 + f], p[q * 129 + f], dsum);
        simr[q] = dsum;
        mx = fmaxf(mx, dsum);
    }
    float sum = 0.f;
    for (int q = 0; q < 64; ++q) { simr[q] = __expf(simr[q] - mx); sum += simr[q]; }
    float inv = 1.f / sum;
    for (int q = 0; q < 64; ++q)
        divb[((size_t)b * 64 + tid) * 64 + q] = 1.f - simr[q] * inv;
}

// ---------------- fp32 SGEMM with packed f32x2 FMA ----------------
__global__ void __launch_bounds__(256) gemm_nt(const float* __restrict__ A,
                                               const float* __restrict__ W,
                                               const float* __restrict__ bias,
                                               float* __restrict__ C,
                                               float scale, int epi) {
    __shared__ float As[8][132];
    __shared__ float Bs[8][132];
    const int tid = threadIdx.x;
    const int m0 = blockIdx.y * 128, n0 = blockIdx.x * 128;
    const int tx = tid & 15, ty = tid >> 4;
    const int lrow = tid >> 1;
    const int lk = (tid & 1) << 2;
    const float* Ap = A + (size_t)(m0 + lrow) * D + lk;
    const float* Wp = W + (size_t)(n0 + lrow) * D + lk;

    ull acc[8][4];
    #pragma unroll
    for (int i = 0; i < 8; ++i)
        #pragma unroll
        for (int j = 0; j < 4; ++j) acc[i][j] = 0ULL;

    for (int k0 = 0; k0 < D; k0 += 8) {
        float4 a4 = *(const float4*)(Ap + k0);
        float4 w4 = *(const float4*)(Wp + k0);
        __syncthreads();
        As[lk + 0][lrow] = a4.x; As[lk + 1][lrow] = a4.y;
        As[lk + 2][lrow] = a4.z; As[lk + 3][lrow] = a4.w;
        Bs[lk + 0][lrow] = w4.x; Bs[lk + 1][lrow] = w4.y;
        Bs[lk + 2][lrow] = w4.z; Bs[lk + 3][lrow] = w4.w;
        __syncthreads();
        #pragma unroll
        for (int k = 0; k < 8; ++k) {
            float ar[8];
            *(float4*)(ar)     = *(const float4*)(&As[k][ty * 8]);
            *(float4*)(ar + 4) = *(const float4*)(&As[k][ty * 8 + 4]);
            union { float4 v[2]; ull u[4]; } bb;
            bb.v[0] = *(const float4*)(&Bs[k][tx * 8]);
            bb.v[1] = *(const float4*)(&Bs[k][tx * 8 + 4]);
            #pragma unroll
            for (int i = 0; i < 8; ++i) {
                ull a2 = dup2(ar[i]);
                #pragma unroll
                for (int j = 0; j < 4; ++j) fma2(acc[i][j], a2, bb.u[j]);
            }
        }
    }

    float bv[8];
    *(float4*)(bv)     = *(const float4*)(&bias[n0 + tx * 8]);
    *(float4*)(bv + 4) = *(const float4*)(&bias[n0 + tx * 8 + 4]);
    const int nb = n0 + tx * 8;

    if (epi == 0) {
        const int h = nb >> 6, kk = nb & 63;
        #pragma unroll
        for (int i = 0; i < 8; ++i) {
            int m = m0 + ty * 8 + i;
            int b_ = m >> 8, s = m & 255;
            float o[8];
            #pragma unroll
            for (int j = 0; j < 4; ++j) {
                float2 p = unp2(acc[i][j]); o[2 * j] = p.x; o[2 * j + 1] = p.y;
            }
            float4 v0, v1;
            v0.x = (o[0] + bv[0]) * scale; v0.y = (o[1] + bv[1]) * scale;
            v0.z = (o[2] + bv[2]) * scale; v0.w = (o[3] + bv[3]) * scale;
            v1.x = (o[4] + bv[4]) * scale; v1.y = (o[5] + bv[5]) * scale;
            v1.z = (o[6] + bv[6]) * scale; v1.w = (o[7] + bv[7]) * scale;
            size_t dst = (((size_t)(b_ * NH + h) * S_LEN + s) << 6) + kk;
            *(float4*)&C[dst]     = v0;
            *(float4*)&C[dst + 4] = v1;
        }
    } else {
        #pragma unroll
        for (int i = 0; i < 8; ++i) {
            int m = m0 + ty * 8 + i;
            float o[8];
            #pragma unroll
            for (int j = 0; j < 4; ++j) {
                float2 p = unp2(acc[i][j]); o[2 * j] = p.x; o[2 * j + 1] = p.y;
            }
            float4 v0, v1;
            v0.x = o[0] + bv[0]; v0.y = o[1] + bv[1];
            v0.z = o[2] + bv[2]; v0.w = o[3] + bv[3];
            v1.x = o[4] + bv[4]; v1.y = o[5] + bv[5];
            v1.z = o[6] + bv[6]; v1.w = o[7] + bv[7];
            *(float4*)&C[(size_t)m * D + nb]     = v0;
            *(float4*)&C[(size_t)m * D + nb + 4] = v1;
        }
    }
}

// ---------------- fused attention per (b, head): tile-parallel ----------------
__global__ void __launch_bounds__(256) attn_kernel(const float* __restrict__ Q,
                                                   const float* __restrict__ K,
                                                   const float* __restrict__ V,
                                                   const float* __restrict__ Div,
                                                   float* __restrict__ attnb,
                                                   float* __restrict__ awp) {
    extern __shared__ float sm[];
    float* Kt    = sm;                     // 64 x 256 (swizzled, transposed)
    float* Vs    = Kt + 64 * 256;          // 256 x 64
    float* Qt    = Vs + 256 * 64;          // 64 x 64 (swizzled, transposed)
    float* P     = Qt + 64 * 64;           // 64 x PS
    float* s2inv = P + 64 * PS;            // 64

    const int tid = threadIdx.x;
    const int bh = blockIdx.x;
    const int b = bh >> 4, n = bh & 15;
    const size_t base = (size_t)bh * (S_LEN * DK);

    // load Kt (transpose + f4-swizzle) and V
    {
        const float4* K4 = (const float4*)(K + base);
        const float4* V4 = (const float4*)(V + base);
        float4* Vs4 = (float4*)Vs;
        for (int idx4 = tid; idx4 < 4096; idx4 += 256) {
            int c = idx4 >> 4, i4 = idx4 & 15;
            float4 kv = K4[idx4];
            float vals[4]; *(float4*)vals = kv;
            #pragma unroll
            for (int w = 0; w < 4; ++w) {
                int i = (i4 << 2) + w;
                Kt[(i << 8) + ((((c >> 2) ^ i) & 63) << 2) + (c & 3)] = vals[w];
            }
            Vs4[idx4] = V4[idx4];
        }
    }
    // stage 0.1*div into P[0..63][0..63]
    for (int idx = tid; idx < 4096; idx += 256) {
        int r = idx >> 6, c = idx & 63;
        P[r * PS + c] = 0.1f * Div[(((b << 6) + r) << 6) + c];
    }
    __syncthreads();

    const int ty  = tid >> 4, tx  = tid & 15;  // score grid: 4 rows x 16 cols / thread
    const int ty2 = tid >> 3, tx2 = tid & 7;   // AV grid: 2 rows x 8 cols / thread
    float* awp_base = awp + (size_t)bh * (S_LEN * S_LEN);

    const float4* Kt4 = (const float4*)Kt;
    const float4* Qt4 = (const float4*)Qt;

    for (int t = 0; t < 4; ++t) {
        const int r0 = t << 6;
        // load Qt tile (transpose + f4-swizzle)
        {
            const float4* Q4 = (const float4*)(Q + base + ((size_t)r0 << 6));
            for (int idx4 = tid; idx4 < 1024; idx4 += 256) {
                int r = idx4 >> 4, i4 = idx4 & 15;
                float4 qv = Q4[idx4];
                float vals[4]; *(float4*)vals = qv;
                #pragma unroll
                for (int w = 0; w < 4; ++w) {
                    int i = (i4 << 2) + w;
                    Qt[(i << 6) + ((((r >> 2) ^ (i & 15)) & 15) << 2) + (r & 3)] = vals[w];
                }
            }
        }
        __syncthreads();

        // ---- scores: 4 rows x 16 cols per thread, f32x2 ----
        ull acc[4][8];
        #pragma unroll
        for (int i = 0; i < 4; ++i)
            #pragma unroll
            for (int j = 0; j < 8; ++j) acc[i][j] = 0ULL;

        const int cb = tx << 2;
        #pragma unroll 2
        for (int i = 0; i < 64; ++i) {
            float4 q = Qt4[(i << 4) + (ty ^ (i & 15))];
            union { float4 v[4]; ull u[8]; } kk;
            const int xi = i & 63;
            #pragma unroll
            for (int c4 = 0; c4 < 4; ++c4)
                kk.v[c4] = Kt4[(i << 6) + ((cb + c4) ^ xi)];
            ull aq;
            aq = dup2(q.x);
            #pragma unroll
            for (int p = 0; p < 8; ++p) fma2(acc[0][p], aq, kk.u[p]);
            aq = dup2(q.y);
            #pragma unroll
            for (int p = 0; p < 8; ++p) fma2(acc[1][p], aq, kk.u[p]);
            aq = dup2(q.z);
            #pragma unroll
            for (int p = 0; p < 8; ++p) fma2(acc[2][p], aq, kk.u[p]);
            aq = dup2(q.w);
            #pragma unroll
            for (int p = 0; p < 8; ++p) fma2(acc[3][p], aq, kk.u[p]);
        }

        // ---- softmax (plain -> awp, biased -> P) ----
        const bool t0 = (t == 0);
        #pragma unroll
        for (int rr = 0; rr < 4; ++rr) {
            const int rloc = ty * 4 + rr;
            float sc[16];
            #pragma unroll
            for (int p = 0; p < 8; ++p) {
                float2 f = unp2(acc[rr][p]); sc[2 * p] = f.x; sc[2 * p + 1] = f.y;
            }
            float lm = sc[0];
            #pragma unroll
            for (int c = 1; c < 16; ++c) lm = fmaxf(lm, sc[c]);
            float m1 = rmax16(lm);

            float d[16];
            float m2 = m1;
            if (t0) {
                float lmb = lm;
                if (tx < 4) {
                    #pragma unroll
                    for (int c = 0; c < 16; ++c)
                        d[c] = P[rloc * PS + tx * 16 + c];
                    lmb = sc[0] + d[0];
                    #pragma unroll
                    for (int c = 1; c < 16; ++c) lmb = fmaxf(lmb, sc[c] + d[c]);
                }
                m2 = rmax16(lmb);
            }

            float e[16];
            float ls1 = 0.f;
            #pragma unroll
            for (int c = 0; c < 16; ++c) { e[c] = __expf(sc[c] - m1); ls1 += e[c]; }
            float s1 = rsum16(ls1);
            float inv1 = 1.f / s1;

            const int sg = r0 + rloc;
            {
                float4 w0, w1, w2, w3;
                w0.x = e[0] * inv1;  w0.y = e[1] * inv1;  w0.z = e[2] * inv1;  w0.w = e[3] * inv1;
                w1.x = e[4] * inv1;  w1.y = e[5] * inv1;  w1.z = e[6] * inv1;  w1.w = e[7] * inv1;
                w2.x = e[8] * inv1;  w2.y = e[9] * inv1;  w2.z = e[10] * inv1; w2.w = e[11] * inv1;
                w3.x = e[12] * inv1; w3.y = e[13] * inv1; w3.z = e[14] * inv1; w3.w = e[15] * inv1;
                float* dst = awp_base + (size_t)sg * S_LEN + tx * 16;
                *(float4*)(dst)      = w0;
                *(float4*)(dst + 4)  = w1;
                *(float4*)(dst + 8)  = w2;
                *(float4*)(dst + 12) = w3;
            }

            float eb[16];
            if (t0) {
                float rs = __expf(m1 - m2);
                if (tx < 4) {
                    #pragma unroll
                    for (int c = 0; c < 16; ++c) eb[c] = e[c] * rs * __expf(d[c]);
                } else {
                    #pragma unroll
                    for (int c = 0; c < 16; ++c) eb[c] = e[c] * rs;
                }
                float ls2 = 0.f;
                #pragma unroll
                for (int c = 0; c < 16; ++c) ls2 += eb[c];
                float s2 = rsum16(ls2);
                if (tx == 0) s2inv[rloc] = 1.f / s2;
            } else {
                #pragma unroll
                for (int c = 0; c < 16; ++c) eb[c] = e[c];
                if (tx == 0) s2inv[rloc] = inv1;
            }
            float* pd = P + rloc * PS + tx * 16;
            *(float4*)(pd)      = *(float4*)(eb);
            *(float4*)(pd + 4)  = *(float4*)(eb + 4);
            *(float4*)(pd + 8)  = *(float4*)(eb + 8);
            *(float4*)(pd + 12) = *(float4*)(eb + 12);
        }
        __syncthreads();

        // ---- AV: 2 rows x 8 cols per thread, f32x2 ----
        ull av[2][4];
        #pragma unroll
        for (int i = 0; i < 2; ++i)
            #pragma unroll
            for (int j = 0; j < 4; ++j) av[i][j] = 0ULL;

        const float* prow0 = P + (ty2 * 2) * PS;
        const float* prow1 = prow0 + PS;
        const int vb = tx2 << 3;
        #pragma unroll 4
        for (int j = 0; j < 256; ++j) {
            float p0 = prow0[j];
            float p1 = prow1[j];
            union { float4 v[2]; ull u[4]; } vv;
            vv.v[0] = *(const float4*)&Vs[(j << 6) + vb];
            vv.v[1] = *(const float4*)&Vs[(j << 6) + vb + 4];
            ull pp0 = dup2(p0), pp1 = dup2(p1);
            #pragma unroll
            for (int q = 0; q < 4; ++q) {
                fma2(av[0][q], pp0, vv.u[q]);
                fma2(av[1][q], pp1, vv.u[q]);
            }
        }

        #pragma unroll
        for (int rr = 0; rr < 2; ++rr) {
            int rloc = ty2 * 2 + rr;
            int s = r0 + rloc;
            float inv = s2inv[rloc];
            float o[8];
            #pragma unroll
            for (int q = 0; q < 4; ++q) {
                float2 f = unp2(av[rr][q]); o[2 * q] = f.x * inv; o[2 * q + 1] = f.y * inv;
            }
            int bp = 2 * n + (b >> 4);
            int sp = ((b & 15) << 4) | (s >> 4);
            int c0 = ((s & 15) << 6) | vb;
            float* dst = attnb + ((size_t)bp * S_LEN + sp) * D + c0;
            *(float4*)(dst)     = *(float4*)(o);
            *(float4*)(dst + 4) = *(float4*)(o + 4);
        }
        __syncthreads();
    }
}

// ---------------- mean over heads of plain attention weights ----------------
__global__ void awmean_kernel(const float* __restrict__ awp, float* __restrict__ out) {
    int idx = blockIdx.x * blockDim.x + threadIdx.x;
    int b = idx >> 16;
    int r = idx & 65535;
    const float* p = awp + (size_t)b * NH * 65536 + r;
    float sum = 0.f;
    #pragma unroll
    for (int h = 0; h < NH; ++h) sum += p[(size_t)h * 65536];
    out[idx] = sum * (1.f / NH);
}

// ---------------- residual + layernorm ----------------
__global__ void __launch_bounds__(256) ln_kernel(const float* __restrict__ Y,
                                                 const float* __restrict__ X,
                                                 const float* __restrict__ G,
                                                 const float* __restrict__ Bb,
                                                 float* __restrict__ out) {
    __shared__ float red[8];
    const int row = blockIdx.x, tid = threadIdx.x;
    const int lane = tid & 31, w = tid >> 5;
    const size_t off = (size_t)row * D + tid * 4;
    float4 v  = *(const float4*)(Y + off);
    float4 xx = *(const float4*)(X + off);
    v.x += xx.x; v.y += xx.y; v.z += xx.z; v.w += xx.w;

    float s = v.x + v.y + v.z + v.w;
    #pragma unroll
    for (int o = 16; o; o >>= 1) s += __shfl_xor_sync(0xffffffffu, s, o);
    if (lane == 0) red[w] = s;
    __syncthreads();
    float tot = 0.f;
    #pragma unroll
    for (int i = 0; i < 8; ++i) tot += red[i];
    float mu = tot * (1.f / 1024.f);
    __syncthreads();

    float d0 = v.x - mu, d1 = v.y - mu, d2 = v.z - mu, d3 = v.w - mu;
    float sq = d0 * d0 + d1 * d1 + d2 * d2 + d3 * d3;
    #pragma unroll
    for (int o = 16; o; o >>= 1) sq += __shfl_xor_sync(0xffffffffu, sq, o);
    if (lane == 0) red[w] = sq;
    __syncthreads();
    float vtot = 0.f;
    #pragma unroll
    for (int i = 0; i < 8; ++i) vtot += red[i];
    float rstd = rsqrtf(vtot * (1.f / 1024.f) + 1e-5f);

    float4 g4 = *(const float4*)(G  + tid * 4);
    float4 b4 = *(const float4*)(Bb + tid * 4);
    float4 o;
    o.x = d0 * rstd * g4.x + b4.x;
    o.y = d1 * rstd * g4.y + b4.y;
    o.z = d2 * rstd * g4.z + b4.z;
    o.w = d3 * rstd * g4.w + b4.w;
    *(float4*)(out + off) = o;
}

// ---------------- launcher ----------------
extern "C" void kernel_launch(void* const* d_in, const int* in_sizes, int n_in,
                              void* d_out, int out_size) {
    const float* x   = (const float*)d_in[0];
    const float* pf  = (const float*)d_in[1];
    const float* wq  = (const float*)d_in[2];
    const float* bq  = (const float*)d_in[3];
    const float* wk  = (const float*)d_in[4];
    const float* bk  = (const float*)d_in[5];
    const float* wv  = (const float*)d_in[6];
    const float* bv  = (const float*)d_in[7];
    const float* wo  = (const float*)d_in[8];
    const float* bo  = (const float*)d_in[9];
    const float* lng = (const float*)d_in[10];
    const float* lnb = (const float*)d_in[11];

    float* out    = (float*)d_out;
    float* out_aw = out + (size_t)M_ROWS * D;

    float *qp, *kp, *vp, *ap, *yp, *awpp, *divp;
    cudaGetSymbolAddress((void**)&qp,   g_q);
    cudaGetSymbolAddress((void**)&kp,   g_k);
    cudaGetSymbolAddress((void**)&vp,   g_v);
    cudaGetSymbolAddress((void**)&ap,   g_attn);
    cudaGetSymbolAddress((void**)&yp,   g_y);
    cudaGetSymbolAddress((void**)&awpp, g_awp);
    cudaGetSymbolAddress((void**)&divp, g_div);

    div_kernel<<<BATCH, 64>>>(pf, divp);

    dim3 gg(D / 128, M_ROWS / 128);
    gemm_nt<<<gg, 256>>>(x, wq, bq, qp, 0.125f, 0);  // fold 1/sqrt(dk) into Q
    gemm_nt<<<gg, 256>>>(x, wk, bk, kp, 1.0f, 0);
    gemm_nt<<<gg, 256>>>(x, wv, bv, vp, 1.0f, 0);

    const size_t ATTN_SMEM =
        (size_t)(64 * 256 + 256 * 64 + 64 * 64 + 64 * PS + 64) * sizeof(float);
    cudaFuncSetAttribute(attn_kernel, cudaFuncAttributeMaxDynamicSharedMemorySize,
                         (int)ATTN_SMEM);
    attn_kernel<<<BATCH * NH, 256, ATTN_SMEM>>>(qp, kp, vp, divp, ap, awpp);

    awmean_kernel<<<(BATCH * S_LEN * S_LEN) / 1024, 1024>>>(awpp, out_aw);

    gemm_nt<<<gg, 256>>>(ap, wo, bo, yp, 1.0f, 1);
    ln_kernel<<<M_ROWS, 256>>>(yp, x, lng, lnb, out);
}

// round 3
// speedup vs baseline: 2.5639x; 1.9827x over previous
#include <cuda_runtime.h>

typedef unsigned long long ull;

#define M_ROWS 8192   // B*S
#define D      1024
#define S_LEN  256
#define NH     16
#define DK     64
#define BATCH  32
#define PS     260    // attn P tile row stride (floats)
#define SMS    36     // gemm smem row stride (tf32 words), ≡4 mod 32 -> conflict-free
#define TILE_W (128 * SMS)

// ---------------- scratch ----------------
__device__ float g_q[M_ROWS * D];
__device__ float g_k[M_ROWS * D];
__device__ float g_v[M_ROWS * D];
__device__ float g_attn[M_ROWS * D];
__device__ float g_y[M_ROWS * D];
__device__ float g_awp[(size_t)BATCH * NH * S_LEN * S_LEN];
__device__ float g_div[BATCH * 64 * 64];

// ---------------- helpers ----------------
__device__ __forceinline__ ull dup2(float x) {
    ull r; asm("mov.b64 %0,{%1,%1};" : "=l"(r) : "f"(x)); return r;
}
__device__ __forceinline__ void fma2(ull& d, ull a, ull b) {
    asm("fma.rn.f32x2 %0,%1,%2,%0;" : "+l"(d) : "l"(a), "l"(b));
}
__device__ __forceinline__ float2 unp2(ull v) {
    float2 f; asm("mov.b64 {%0,%1},%2;" : "=f"(f.x), "=f"(f.y) : "l"(v)); return f;
}
__device__ __forceinline__ float rmax16(float v) {
    #pragma unroll
    for (int o = 8; o; o >>= 1) v = fmaxf(v, __shfl_xor_sync(0xffffffffu, v, o));
    return v;
}
__device__ __forceinline__ float rsum16(float v) {
    #pragma unroll
    for (int o = 8; o; o >>= 1) v += __shfl_xor_sync(0xffffffffu, v, o);
    return v;
}
__device__ __forceinline__ unsigned t32(float f) {
    unsigned u; asm("cvt.rna.tf32.f32 %0,%1;" : "=r"(u) : "f"(f)); return u;
}
__device__ __forceinline__ uint4 t32x4(float4 v) {
    uint4 u; u.x = t32(v.x); u.y = t32(v.y); u.z = t32(v.z); u.w = t32(v.w); return u;
}
__device__ __forceinline__ void mma8(float* c, const unsigned* a, const unsigned* b) {
    asm("mma.sync.aligned.m16n8k8.row.col.f32.tf32.tf32.f32 "
        "{%0,%1,%2,%3},{%4,%5,%6,%7},{%8,%9},{%0,%1,%2,%3};"
        : "+f"(c[0]), "+f"(c[1]), "+f"(c[2]), "+f"(c[3])
        : "r"(a[0]), "r"(a[1]), "r"(a[2]), "r"(a[3]), "r"(b[0]), "r"(b[1]));
}

// ---------------- div bias ----------------
__global__ void div_kernel(const float* __restrict__ pf, float* __restrict__ divb) {
    __shared__ float p[64 * 129];
    const int b = blockIdx.x;
    const int tid = threadIdx.x;  // 64 threads
    for (int idx = tid; idx < 64 * 128; idx += 64) {
        int r = idx >> 7, f = idx & 127;
        p[r * 129 + f] = pf[(size_t)b * 64 * 128 + idx];
    }
    __syncthreads();
    float simr[64];
    float mx = -1e30f;
    for (int q = 0; q < 64; ++q) {
        float dsum = 0.f;
        #pragma unroll 8
        for (int f = 0; f < 128; ++f)
            dsum = fmaf(p[tid * 129 + f], p[q * 129 + f], dsum);
        simr[q] = dsum;
        mx = fmaxf(mx, dsum);
    }
    float sum = 0.f;
    for (int q = 0; q < 64; ++q) { simr[q] = __expf(simr[q] - mx); sum += simr[q]; }
    float inv = 1.f / sum;
    for (int q = 0; q < 64; ++q)
        divb[((size_t)b * 64 + tid) * 64 + q] = 1.f - simr[q] * inv;
}

// ---------------- TF32 tensor-core GEMM: C[m,n] = sum_k A[m,k]*W[n,k] ----------------
__global__ void __launch_bounds__(256) gemm_tf32(const float* __restrict__ A,
                                                 const float* __restrict__ W,
                                                 const float* __restrict__ bias,
                                                 float* __restrict__ C,
                                                 float scale, int epi) {
    extern __shared__ unsigned smu[];
    unsigned* AsB = smu;               // 2 buffers x 128 x SMS
    unsigned* BsB = smu + 2 * TILE_W;

    const int tid = threadIdx.x;
    const int m0 = blockIdx.y * 128, n0 = blockIdx.x * 128;
    const int lr = tid >> 3, lc = (tid & 7) * 4;
    const float* Ap = A + (size_t)(m0 + lr) * D + lc;
    const float* Wp = W + (size_t)(n0 + lr) * D + lc;

    const int wid = tid >> 5, lane = tid & 31;
    const int g = lane >> 2, tg = lane & 3;
    const int wm = (wid & 3) * 32, wn = (wid >> 2) * 64;

    float acc[2][8][4];
    #pragma unroll
    for (int mi = 0; mi < 2; ++mi)
        #pragma unroll
        for (int ni = 0; ni < 8; ++ni)
            #pragma unroll
            for (int q = 0; q < 4; ++q) acc[mi][ni][q] = 0.f;

    // stage k-tile 0
    #pragma unroll
    for (int p = 0; p < 4; ++p) {
        float4 a4 = *(const float4*)(Ap + (size_t)p * 32 * D);
        float4 w4 = *(const float4*)(Wp + (size_t)p * 32 * D);
        *(uint4*)&AsB[(lr + 32 * p) * SMS + lc] = t32x4(a4);
        *(uint4*)&BsB[(lr + 32 * p) * SMS + lc] = t32x4(w4);
    }
    __syncthreads();

    for (int kt = 0; kt < 32; ++kt) {
        const int cur = (kt & 1) * TILE_W, nxt = ((kt + 1) & 1) * TILE_W;
        float4 pa[4], pw[4];
        if (kt < 31) {
            #pragma unroll
            for (int p = 0; p < 4; ++p) {
                pa[p] = *(const float4*)(Ap + (size_t)p * 32 * D + (kt + 1) * 32);
                pw[p] = *(const float4*)(Wp + (size_t)p * 32 * D + (kt + 1) * 32);
            }
        }
        const unsigned* Ac = AsB + cur;
        const unsigned* Bc = BsB + cur;
        #pragma unroll
        for (int ks = 0; ks < 4; ++ks) {
            const int kk = ks * 8 + tg;
            unsigned af[2][4], bf[8][2];
            #pragma unroll
            for (int mi = 0; mi < 2; ++mi) {
                int base = (wm + mi * 16 + g) * SMS + kk;
                af[mi][0] = Ac[base];
                af[mi][1] = Ac[base + 8 * SMS];
                af[mi][2] = Ac[base + 4];
                af[mi][3] = Ac[base + 8 * SMS + 4];
            }
            #pragma unroll
            for (int ni = 0; ni < 8; ++ni) {
                int base = (wn + ni * 8 + g) * SMS + kk;
                bf[ni][0] = Bc[base];
                bf[ni][1] = Bc[base + 4];
            }
            #pragma unroll
            for (int mi = 0; mi < 2; ++mi)
                #pragma unroll
                for (int ni = 0; ni < 8; ++ni)
                    mma8(acc[mi][ni], af[mi], bf[ni]);
        }
        if (kt < 31) {
            #pragma unroll
            for (int p = 0; p < 4; ++p) {
                *(uint4*)&AsB[nxt + (lr + 32 * p) * SMS + lc] = t32x4(pa[p]);
                *(uint4*)&BsB[nxt + (lr + 32 * p) * SMS + lc] = t32x4(pw[p]);
            }
        }
        __syncthreads();
    }

    // epilogue
    float2 bfr[8];
    #pragma unroll
    for (int ni = 0; ni < 8; ++ni)
        bfr[ni] = *(const float2*)&bias[n0 + wn + ni * 8 + 2 * tg];

    if (epi == 0) {
        #pragma unroll
        for (int mi = 0; mi < 2; ++mi) {
            const int mbase = m0 + wm + mi * 16 + g;
            #pragma unroll
            for (int r = 0; r < 2; ++r) {
                int m = mbase + r * 8;
                int b_ = m >> 8, s = m & 255;
                #pragma unroll
                for (int ni = 0; ni < 8; ++ni) {
                    int n = n0 + wn + ni * 8 + 2 * tg;
                    int h = n >> 6, kk = n & 63;
                    float2 o;
                    o.x = (acc[mi][ni][2 * r + 0] + bfr[ni].x) * scale;
                    o.y = (acc[mi][ni][2 * r + 1] + bfr[ni].y) * scale;
                    *(float2*)&C[(((size_t)(b_ * NH + h) * S_LEN + s) << 6) + kk] = o;
                }
            }
        }
    } else {
        #pragma unroll
        for (int mi = 0; mi < 2; ++mi) {
            const int mbase = m0 + wm + mi * 16 + g;
            #pragma unroll
            for (int r = 0; r < 2; ++r) {
                int m = mbase + r * 8;
                #pragma unroll
                for (int ni = 0; ni < 8; ++ni) {
                    int n = n0 + wn + ni * 8 + 2 * tg;
                    float2 o;
                    o.x = acc[mi][ni][2 * r + 0] + bfr[ni].x;
                    o.y = acc[mi][ni][2 * r + 1] + bfr[ni].y;
                    *(float2*)&C[(size_t)m * D + n] = o;
                }
            }
        }
    }
}

// ---------------- fused attention per (b, head): tile-parallel ----------------
__global__ void __launch_bounds__(256) attn_kernel(const float* __restrict__ Q,
                                                   const float* __restrict__ K,
                                                   const float* __restrict__ V,
                                                   const float* __restrict__ Div,
                                                   float* __restrict__ attnb,
                                                   float* __restrict__ awp) {
    extern __shared__ float sm[];
    float* Kt    = sm;                     // 64 x 256 (swizzled, transposed)
    float* Vs    = Kt + 64 * 256;          // 256 x 64
    float* Qt    = Vs + 256 * 64;          // 64 x 64 (swizzled, transposed)
    float* P     = Qt + 64 * 64;           // 64 x PS
    float* s2inv = P + 64 * PS;            // 64

    const int tid = threadIdx.x;
    const int bh = blockIdx.x;
    const int b = bh >> 4, n = bh & 15;
    const size_t base = (size_t)bh * (S_LEN * DK);

    {
        const float4* K4 = (const float4*)(K + base);
        const float4* V4 = (const float4*)(V + base);
        float4* Vs4 = (float4*)Vs;
        for (int idx4 = tid; idx4 < 4096; idx4 += 256) {
            int c = idx4 >> 4, i4 = idx4 & 15;
            float4 kv = K4[idx4];
            float vals[4]; *(float4*)vals = kv;
            #pragma unroll
            for (int w = 0; w < 4; ++w) {
                int i = (i4 << 2) + w;
                Kt[(i << 8) + ((((c >> 2) ^ i) & 63) << 2) + (c & 3)] = vals[w];
            }
            Vs4[idx4] = V4[idx4];
        }
    }
    for (int idx = tid; idx < 4096; idx += 256) {
        int r = idx >> 6, c = idx & 63;
        P[r * PS + c] = 0.1f * Div[(((b << 6) + r) << 6) + c];
    }
    __syncthreads();

    const int ty  = tid >> 4, tx  = tid & 15;
    const int ty2 = tid >> 3, tx2 = tid & 7;
    float* awp_base = awp + (size_t)bh * (S_LEN * S_LEN);

    const float4* Kt4 = (const float4*)Kt;
    const float4* Qt4 = (const float4*)Qt;

    for (int t = 0; t < 4; ++t) {
        const int r0 = t << 6;
        {
            const float4* Q4 = (const float4*)(Q + base + ((size_t)r0 << 6));
            for (int idx4 = tid; idx4 < 1024; idx4 += 256) {
                int r = idx4 >> 4, i4 = idx4 & 15;
                float4 qv = Q4[idx4];
                float vals[4]; *(float4*)vals = qv;
                #pragma unroll
                for (int w = 0; w < 4; ++w) {
                    int i = (i4 << 2) + w;
                    Qt[(i << 6) + ((((r >> 2) ^ (i & 15)) & 15) << 2) + (r & 3)] = vals[w];
                }
            }
        }
        __syncthreads();

        ull acc[4][8];
        #pragma unroll
        for (int i = 0; i < 4; ++i)
            #pragma unroll
            for (int j = 0; j < 8; ++j) acc[i][j] = 0ULL;

        const int cb = tx << 2;
        #pragma unroll 2
        for (int i = 0; i < 64; ++i) {
            float4 q = Qt4[(i << 4) + (ty ^ (i & 15))];
            union { float4 v[4]; ull u[8]; } kk;
            const int xi = i & 63;
            #pragma unroll
            for (int c4 = 0; c4 < 4; ++c4)
                kk.v[c4] = Kt4[(i << 6) + ((cb + c4) ^ xi)];
            ull aq;
            aq = dup2(q.x);
            #pragma unroll
            for (int p = 0; p < 8; ++p) fma2(acc[0][p], aq, kk.u[p]);
            aq = dup2(q.y);
            #pragma unroll
            for (int p = 0; p < 8; ++p) fma2(acc[1][p], aq, kk.u[p]);
            aq = dup2(q.z);
            #pragma unroll
            for (int p = 0; p < 8; ++p) fma2(acc[2][p], aq, kk.u[p]);
            aq = dup2(q.w);
            #pragma unroll
            for (int p = 0; p < 8; ++p) fma2(acc[3][p], aq, kk.u[p]);
        }

        const bool t0 = (t == 0);
        #pragma unroll
        for (int rr = 0; rr < 4; ++rr) {
            const int rloc = ty * 4 + rr;
            float sc[16];
            #pragma unroll
            for (int p = 0; p < 8; ++p) {
                float2 f = unp2(acc[rr][p]); sc[2 * p] = f.x; sc[2 * p + 1] = f.y;
            }
            float lm = sc[0];
            #pragma unroll
            for (int c = 1; c < 16; ++c) lm = fmaxf(lm, sc[c]);
            float m1 = rmax16(lm);

            float d[16];
            float m2 = m1;
            if (t0) {
                float lmb = lm;
                if (tx < 4) {
                    #pragma unroll
                    for (int c = 0; c < 16; ++c)
                        d[c] = P[rloc * PS + tx * 16 + c];
                    lmb = sc[0] + d[0];
                    #pragma unroll
                    for (int c = 1; c < 16; ++c) lmb = fmaxf(lmb, sc[c] + d[c]);
                }
                m2 = rmax16(lmb);
            }

            float e[16];
            float ls1 = 0.f;
            #pragma unroll
            for (int c = 0; c < 16; ++c) { e[c] = __expf(sc[c] - m1); ls1 += e[c]; }
            float s1 = rsum16(ls1);
            float inv1 = 1.f / s1;

            const int sg = r0 + rloc;
            {
                float4 w0, w1, w2, w3;
                w0.x = e[0] * inv1;  w0.y = e[1] * inv1;  w0.z = e[2] * inv1;  w0.w = e[3] * inv1;
                w1.x = e[4] * inv1;  w1.y = e[5] * inv1;  w1.z = e[6] * inv1;  w1.w = e[7] * inv1;
                w2.x = e[8] * inv1;  w2.y = e[9] * inv1;  w2.z = e[10] * inv1; w2.w = e[11] * inv1;
                w3.x = e[12] * inv1; w3.y = e[13] * inv1; w3.z = e[14] * inv1; w3.w = e[15] * inv1;
                float* dst = awp_base + (size_t)sg * S_LEN + tx * 16;
                *(float4*)(dst)      = w0;
                *(float4*)(dst + 4)  = w1;
                *(float4*)(dst + 8)  = w2;
                *(float4*)(dst + 12) = w3;
            }

            float eb[16];
            if (t0) {
                float rs = __expf(m1 - m2);
                if (tx < 4) {
                    #pragma unroll
                    for (int c = 0; c < 16; ++c) eb[c] = e[c] * rs * __expf(d[c]);
                } else {
                    #pragma unroll
                    for (int c = 0; c < 16; ++c) eb[c] = e[c] * rs;
                }
                float ls2 = 0.f;
                #pragma unroll
                for (int c = 0; c < 16; ++c) ls2 += eb[c];
                float s2 = rsum16(ls2);
                if (tx == 0) s2inv[rloc] = 1.f / s2;
            } else {
                #pragma unroll
                for (int c = 0; c < 16; ++c) eb[c] = e[c];
                if (tx == 0) s2inv[rloc] = inv1;
            }
            float* pd = P + rloc * PS + tx * 16;
            *(float4*)(pd)      = *(float4*)(eb);
            *(float4*)(pd + 4)  = *(float4*)(eb + 4);
            *(float4*)(pd + 8)  = *(float4*)(eb + 8);
            *(float4*)(pd + 12) = *(float4*)(eb + 12);
        }
        __syncthreads();

        ull av[2][4];
        #pragma unroll
        for (int i = 0; i < 2; ++i)
            #pragma unroll
            for (int j = 0; j < 4; ++j) av[i][j] = 0ULL;

        const float* prow0 = P + (ty2 * 2) * PS;
        const float* prow1 = prow0 + PS;
        const int vb = tx2 << 3;
        #pragma unroll 4
        for (int j = 0; j < 256; ++j) {
            float p0 = prow0[j];
            float p1 = prow1[j];
            union { float4 v[2]; ull u[4]; } vv;
            vv.v[0] = *(const float4*)&Vs[(j << 6) + vb];
            vv.v[1] = *(const float4*)&Vs[(j << 6) + vb + 4];
            ull pp0 = dup2(p0), pp1 = dup2(p1);
            #pragma unroll
            for (int q = 0; q < 4; ++q) {
                fma2(av[0][q], pp0, vv.u[q]);
                fma2(av[1][q], pp1, vv.u[q]);
            }
        }

        #pragma unroll
        for (int rr = 0; rr < 2; ++rr) {
            int rloc = ty2 * 2 + rr;
            int s = r0 + rloc;
            float inv = s2inv[rloc];
            float o[8];
            #pragma unroll
            for (int q = 0; q < 4; ++q) {
                float2 f = unp2(av[rr][q]); o[2 * q] = f.x * inv; o[2 * q + 1] = f.y * inv;
            }
            int bp = 2 * n + (b >> 4);
            int sp = ((b & 15) << 4) | (s >> 4);
            int c0 = ((s & 15) << 6) | vb;
            float* dst = attnb + ((size_t)bp * S_LEN + sp) * D + c0;
            *(float4*)(dst)     = *(float4*)(o);
            *(float4*)(dst + 4) = *(float4*)(o + 4);
        }
        __syncthreads();
    }
}

// ---------------- mean over heads ----------------
__global__ void awmean_kernel(const float* __restrict__ awp, float* __restrict__ out) {
    int idx = blockIdx.x * blockDim.x + threadIdx.x;
    int b = idx >> 16;
    int r = idx & 65535;
    const float* p = awp + (size_t)b * NH * 65536 + r;
    float sum = 0.f;
    #pragma unroll
    for (int h = 0; h < NH; ++h) sum += p[(size_t)h * 65536];
    out[idx] = sum * (1.f / NH);
}

// ---------------- residual + layernorm ----------------
__global__ void __launch_bounds__(256) ln_kernel(const float* __restrict__ Y,
                                                 const float* __restrict__ X,
                                                 const float* __restrict__ G,
                                                 const float* __restrict__ Bb,
                                                 float* __restrict__ out) {
    __shared__ float red[8];
    const int row = blockIdx.x, tid = threadIdx.x;
    const int lane = tid & 31, w = tid >> 5;
    const size_t off = (size_t)row * D + tid * 4;
    float4 v  = *(const float4*)(Y + off);
    float4 xx = *(const float4*)(X + off);
    v.x += xx.x; v.y += xx.y; v.z += xx.z; v.w += xx.w;

    float s = v.x + v.y + v.z + v.w;
    #pragma unroll
    for (int o = 16; o; o >>= 1) s += __shfl_xor_sync(0xffffffffu, s, o);
    if (lane == 0) red[w] = s;
    __syncthreads();
    float tot = 0.f;
    #pragma unroll
    for (int i = 0; i < 8; ++i) tot += red[i];
    float mu = tot * (1.f / 1024.f);
    __syncthreads();

    float d0 = v.x - mu, d1 = v.y - mu, d2 = v.z - mu, d3 = v.w - mu;
    float sq = d0 * d0 + d1 * d1 + d2 * d2 + d3 * d3;
    #pragma unroll
    for (int o = 16; o; o >>= 1) sq += __shfl_xor_sync(0xffffffffu, sq, o);
    if (lane == 0) red[w] = sq;
    __syncthreads();
    float vtot = 0.f;
    #pragma unroll
    for (int i = 0; i < 8; ++i) vtot += red[i];
    float rstd = rsqrtf(vtot * (1.f / 1024.f) + 1e-5f);

    float4 g4 = *(const float4*)(G  + tid * 4);
    float4 b4 = *(const float4*)(Bb + tid * 4);
    float4 o;
    o.x = d0 * rstd * g4.x + b4.x;
    o.y = d1 * rstd * g4.y + b4.y;
    o.z = d2 * rstd * g4.z + b4.z;
    o.w = d3 * rstd * g4.w + b4.w;
    *(float4*)(out + off) = o;
}

// ---------------- launcher ----------------
extern "C" void kernel_launch(void* const* d_in, const int* in_sizes, int n_in,
                              void* d_out, int out_size) {
    const float* x   = (const float*)d_in[0];
    const float* pf  = (const float*)d_in[1];
    const float* wq  = (const float*)d_in[2];
    const float* bq  = (const float*)d_in[3];
    const float* wk  = (const float*)d_in[4];
    const float* bk  = (const float*)d_in[5];
    const float* wv  = (const float*)d_in[6];
    const float* bv  = (const float*)d_in[7];
    const float* wo  = (const float*)d_in[8];
    const float* bo  = (const float*)d_in[9];
    const float* lng = (const float*)d_in[10];
    const float* lnb = (const float*)d_in[11];

    float* out    = (float*)d_out;
    float* out_aw = out + (size_t)M_ROWS * D;

    float *qp, *kp, *vp, *ap, *yp, *awpp, *divp;
    cudaGetSymbolAddress((void**)&qp,   g_q);
    cudaGetSymbolAddress((void**)&kp,   g_k);
    cudaGetSymbolAddress((void**)&vp,   g_v);
    cudaGetSymbolAddress((void**)&ap,   g_attn);
    cudaGetSymbolAddress((void**)&yp,   g_y);
    cudaGetSymbolAddress((void**)&awpp, g_awp);
    cudaGetSymbolAddress((void**)&divp, g_div);

    div_kernel<<<BATCH, 64>>>(pf, divp);

    const int GEMM_SMEM = 4 * TILE_W * 4;  // 73728 bytes
    cudaFuncSetAttribute(gemm_tf32, cudaFuncAttributeMaxDynamicSharedMemorySize,
                         GEMM_SMEM);

    dim3 gg(D / 128, M_ROWS / 128);
    gemm_tf32<<<gg, 256, GEMM_SMEM>>>(x, wq, bq, qp, 0.125f, 0);
    gemm_tf32<<<gg, 256, GEMM_SMEM>>>(x, wk, bk, kp, 1.0f, 0);
    gemm_tf32<<<gg, 256, GEMM_SMEM>>>(x, wv, bv, vp, 1.0f, 0);

    const size_t ATTN_SMEM =
        (size_t)(64 * 256 + 256 * 64 + 64 * 64 + 64 * PS + 64) * sizeof(float);
    cudaFuncSetAttribute(attn_kernel, cudaFuncAttributeMaxDynamicSharedMemorySize,
                         (int)ATTN_SMEM);
    attn_kernel<<<BATCH * NH, 256, ATTN_SMEM>>>(qp, kp, vp, divp, ap, awpp);

    awmean_kernel<<<(BATCH * S_LEN * S_LEN) / 1024, 1024>>>(awpp, out_aw);

    gemm_tf32<<<gg, 256, GEMM_SMEM>>>(ap, wo, bo, yp, 1.0f, 1);
    ln_kernel<<<M_ROWS, 256>>>(yp, x, lng, lnb, out);
}

// round 4
// speedup vs baseline: 3.9874x; 1.5552x over previous
#include <cuda_runtime.h>

#define M_ROWS 8192   // B*S
#define D      1024
#define S_LEN  256
#define NH     16
#define DK     64
#define BATCH  32
#define SMS    36     // gemm smem row stride (tf32 words)
#define TILE_W (128 * SMS)

#define KS_S   68     // K/Q smem row stride (words), ≡4 mod 32
#define VS_S   260    // Vt/P smem row stride (words), ≡4 mod 32

// ---------------- scratch ----------------
__device__ float g_q[M_ROWS * D];
__device__ float g_k[M_ROWS * D];
__device__ float g_v[M_ROWS * D];
__device__ float g_attn[M_ROWS * D];
__device__ float g_y[M_ROWS * D];
__device__ float g_awp[(size_t)BATCH * NH * S_LEN * S_LEN];
__device__ float g_div[BATCH * 64 * 64];

// ---------------- helpers ----------------
__device__ __forceinline__ unsigned t32(float f) {
    unsigned u; asm("cvt.rna.tf32.f32 %0,%1;" : "=r"(u) : "f"(f)); return u;
}
__device__ __forceinline__ uint4 t32x4(float4 v) {
    uint4 u; u.x = t32(v.x); u.y = t32(v.y); u.z = t32(v.z); u.w = t32(v.w); return u;
}
__device__ __forceinline__ void mma8(float* c, const unsigned* a, const unsigned* b) {
    asm("mma.sync.aligned.m16n8k8.row.col.f32.tf32.tf32.f32 "
        "{%0,%1,%2,%3},{%4,%5,%6,%7},{%8,%9},{%0,%1,%2,%3};"
        : "+f"(c[0]), "+f"(c[1]), "+f"(c[2]), "+f"(c[3])
        : "r"(a[0]), "r"(a[1]), "r"(a[2]), "r"(a[3]), "r"(b[0]), "r"(b[1]));
}

// ---------------- div bias ----------------
__global__ void div_kernel(const float* __restrict__ pf, float* __restrict__ divb) {
    __shared__ float p[64 * 129];
    const int b = blockIdx.x;
    const int tid = threadIdx.x;  // 64 threads
    for (int idx = tid; idx < 64 * 128; idx += 64) {
        int r = idx >> 7, f = idx & 127;
        p[r * 129 + f] = pf[(size_t)b * 64 * 128 + idx];
    }
    __syncthreads();
    float simr[64];
    float mx = -1e30f;
    for (int q = 0; q < 64; ++q) {
        float dsum = 0.f;
        #pragma unroll 8
        for (int f = 0; f < 128; ++f)
            dsum = fmaf(p[tid * 129 + f], p[q * 129 + f], dsum);
        simr[q] = dsum;
        mx = fmaxf(mx, dsum);
    }
    float sum = 0.f;
    for (int q = 0; q < 64; ++q) { simr[q] = __expf(simr[q] - mx); sum += simr[q]; }
    float inv = 1.f / sum;
    for (int q = 0; q < 64; ++q)
        divb[((size_t)b * 64 + tid) * 64 + q] = 1.f - simr[q] * inv;
}

// ---------------- TF32 tensor-core GEMM ----------------
__global__ void __launch_bounds__(256) gemm_tf32(const float* __restrict__ A,
                                                 const float* __restrict__ W,
                                                 const float* __restrict__ bias,
                                                 float* __restrict__ C,
                                                 float scale, int epi) {
    extern __shared__ unsigned smu[];
    unsigned* AsB = smu;
    unsigned* BsB = smu + 2 * TILE_W;

    const int tid = threadIdx.x;
    const int m0 = blockIdx.y * 128, n0 = blockIdx.x * 128;
    const int lr = tid >> 3, lc = (tid & 7) * 4;
    const float* Ap = A + (size_t)(m0 + lr) * D + lc;
    const float* Wp = W + (size_t)(n0 + lr) * D + lc;

    const int wid = tid >> 5, lane = tid & 31;
    const int g = lane >> 2, tg = lane & 3;
    const int wm = (wid & 3) * 32, wn = (wid >> 2) * 64;

    float acc[2][8][4];
    #pragma unroll
    for (int mi = 0; mi < 2; ++mi)
        #pragma unroll
        for (int ni = 0; ni < 8; ++ni)
            #pragma unroll
            for (int q = 0; q < 4; ++q) acc[mi][ni][q] = 0.f;

    #pragma unroll
    for (int p = 0; p < 4; ++p) {
        float4 a4 = *(const float4*)(Ap + (size_t)p * 32 * D);
        float4 w4 = *(const float4*)(Wp + (size_t)p * 32 * D);
        *(uint4*)&AsB[(lr + 32 * p) * SMS + lc] = t32x4(a4);
        *(uint4*)&BsB[(lr + 32 * p) * SMS + lc] = t32x4(w4);
    }
    __syncthreads();

    for (int kt = 0; kt < 32; ++kt) {
        const int cur = (kt & 1) * TILE_W, nxt = ((kt + 1) & 1) * TILE_W;
        float4 pa[4], pw[4];
        if (kt < 31) {
            #pragma unroll
            for (int p = 0; p < 4; ++p) {
                pa[p] = *(const float4*)(Ap + (size_t)p * 32 * D + (kt + 1) * 32);
                pw[p] = *(const float4*)(Wp + (size_t)p * 32 * D + (kt + 1) * 32);
            }
        }
        const unsigned* Ac = AsB + cur;
        const unsigned* Bc = BsB + cur;
        #pragma unroll
        for (int ks = 0; ks < 4; ++ks) {
            const int kk = ks * 8 + tg;
            unsigned af[2][4], bf[8][2];
            #pragma unroll
            for (int mi = 0; mi < 2; ++mi) {
                int base = (wm + mi * 16 + g) * SMS + kk;
                af[mi][0] = Ac[base];
                af[mi][1] = Ac[base + 8 * SMS];
                af[mi][2] = Ac[base + 4];
                af[mi][3] = Ac[base + 8 * SMS + 4];
            }
            #pragma unroll
            for (int ni = 0; ni < 8; ++ni) {
                int base = (wn + ni * 8 + g) * SMS + kk;
                bf[ni][0] = Bc[base];
                bf[ni][1] = Bc[base + 4];
            }
            #pragma unroll
            for (int mi = 0; mi < 2; ++mi)
                #pragma unroll
                for (int ni = 0; ni < 8; ++ni)
                    mma8(acc[mi][ni], af[mi], bf[ni]);
        }
        if (kt < 31) {
            #pragma unroll
            for (int p = 0; p < 4; ++p) {
                *(uint4*)&AsB[nxt + (lr + 32 * p) * SMS + lc] = t32x4(pa[p]);
                *(uint4*)&BsB[nxt + (lr + 32 * p) * SMS + lc] = t32x4(pw[p]);
            }
        }
        __syncthreads();
    }

    float2 bfr[8];
    #pragma unroll
    for (int ni = 0; ni < 8; ++ni)
        bfr[ni] = *(const float2*)&bias[n0 + wn + ni * 8 + 2 * tg];

    if (epi == 0) {
        #pragma unroll
        for (int mi = 0; mi < 2; ++mi) {
            const int mbase = m0 + wm + mi * 16 + g;
            #pragma unroll
            for (int r = 0; r < 2; ++r) {
                int m = mbase + r * 8;
                int b_ = m >> 8, s = m & 255;
                #pragma unroll
                for (int ni = 0; ni < 8; ++ni) {
                    int n = n0 + wn + ni * 8 + 2 * tg;
                    int h = n >> 6, kk = n & 63;
                    float2 o;
                    o.x = (acc[mi][ni][2 * r + 0] + bfr[ni].x) * scale;
                    o.y = (acc[mi][ni][2 * r + 1] + bfr[ni].y) * scale;
                    *(float2*)&C[(((size_t)(b_ * NH + h) * S_LEN + s) << 6) + kk] = o;
                }
            }
        }
    } else {
        #pragma unroll
        for (int mi = 0; mi < 2; ++mi) {
            const int mbase = m0 + wm + mi * 16 + g;
            #pragma unroll
            for (int r = 0; r < 2; ++r) {
                int m = mbase + r * 8;
                #pragma unroll
                for (int ni = 0; ni < 8; ++ni) {
                    int n = n0 + wn + ni * 8 + 2 * tg;
                    float2 o;
                    o.x = acc[mi][ni][2 * r + 0] + bfr[ni].x;
                    o.y = acc[mi][ni][2 * r + 1] + bfr[ni].y;
                    *(float2*)&C[(size_t)m * D + n] = o;
                }
            }
        }
    }
}

// ---------------- tensor-core fused attention per (b, head) ----------------
__global__ void __launch_bounds__(256) attn_tc(const float* __restrict__ Q,
                                               const float* __restrict__ K,
                                               const float* __restrict__ V,
                                               const float* __restrict__ Div,
                                               float* __restrict__ attnb,
                                               float* __restrict__ awp) {
    extern __shared__ unsigned smu[];
    unsigned* Ks = smu;                      // [256][KS_S]
    unsigned* Vt = Ks + 256 * KS_S;          // [64][VS_S]  (V transposed: [dk][s])
    unsigned* Qs = Vt + 64 * VS_S;           // [64][KS_S]
    unsigned* Pm = Qs + 64 * KS_S;           // [64][VS_S]  (tf32 P / fp32 bias stage)
    float* red = (float*)(Pm + 64 * VS_S);   // [3][4][64]

    const int tid = threadIdx.x;
    const int bh = blockIdx.x, b = bh >> 4, n = bh & 15;
    const size_t base = (size_t)bh * (S_LEN * DK);

    // load K (tf32) + V transposed (tf32); stage 0.1*div bias into Pm as float
    {
        const float4* K4 = (const float4*)(K + base);
        const float4* V4 = (const float4*)(V + base);
        for (int idx4 = tid; idx4 < 4096; idx4 += 256) {
            int r = idx4 >> 4, c4 = (idx4 & 15) << 2;
            *(uint4*)&Ks[r * KS_S + c4] = t32x4(K4[idx4]);
            float4 v = V4[idx4];
            Vt[(c4 + 0) * VS_S + r] = t32(v.x);
            Vt[(c4 + 1) * VS_S + r] = t32(v.y);
            Vt[(c4 + 2) * VS_S + r] = t32(v.z);
            Vt[(c4 + 3) * VS_S + r] = t32(v.w);
        }
        float* Pf = (float*)Pm;
        for (int idx = tid; idx < 4096; idx += 256) {
            int r = idx >> 6, c = idx & 63;
            Pf[r * VS_S + c] = 0.1f * Div[(((b << 6) + r) << 6) + c];
        }
    }

    const int lane = tid & 31, wid = tid >> 5;
    const int g = lane >> 2, tg = lane & 3;
    const int s_wm = (wid & 1) * 32;          // scores: 2 m-tiles of 16
    const int warp_n = wid >> 1;
    const int s_wn = warp_n * 64;             // scores: 8 n8-tiles
    const int a_wm = (wid & 1) * 32;          // AV: 2 m-tiles
    const int a_wn = (wid >> 1) * 16;         // AV: 2 n8-tiles

    float* awp_base = awp + (size_t)bh * (S_LEN * S_LEN);
    float* Pf = (float*)Pm;
    float* redm  = red;
    float* reds1 = red + 256;
    float* reds2 = red + 512;
    const int bp = 2 * n + (b >> 4);

    for (int t = 0; t < 4; ++t) {
        const int r0 = t << 6;
        // load Q tile (tf32)
        {
            const float4* Q4 = (const float4*)(Q + base + ((size_t)r0 << 6));
            for (int idx4 = tid; idx4 < 1024; idx4 += 256) {
                int r = idx4 >> 4, c4 = (idx4 & 15) << 2;
                *(uint4*)&Qs[r * KS_S + c4] = t32x4(Q4[idx4]);
            }
        }
        __syncthreads();

        // ---- scores: 64x256, k=64 ----
        float sacc[2][8][4];
        #pragma unroll
        for (int mi = 0; mi < 2; ++mi)
            #pragma unroll
            for (int ni = 0; ni < 8; ++ni)
                #pragma unroll
                for (int q = 0; q < 4; ++q) sacc[mi][ni][q] = 0.f;

        #pragma unroll
        for (int ks = 0; ks < 8; ++ks) {
            const int kk = ks * 8 + tg;
            unsigned af[2][4], bf[8][2];
            #pragma unroll
            for (int mi = 0; mi < 2; ++mi) {
                int ar = (s_wm + mi * 16 + g) * KS_S + kk;
                af[mi][0] = Qs[ar];
                af[mi][1] = Qs[ar + 8 * KS_S];
                af[mi][2] = Qs[ar + 4];
                af[mi][3] = Qs[ar + 8 * KS_S + 4];
            }
            #pragma unroll
            for (int ni = 0; ni < 8; ++ni) {
                int br = (s_wn + ni * 8 + g) * KS_S + kk;
                bf[ni][0] = Ks[br];
                bf[ni][1] = Ks[br + 4];
            }
            #pragma unroll
            for (int mi = 0; mi < 2; ++mi)
                #pragma unroll
                for (int ni = 0; ni < 8; ++ni)
                    mma8(sacc[mi][ni], af[mi], bf[ni]);
        }

        // ---- softmax: single shared max (shift-invariant for biased variant) ----
        const bool bias_w = (t == 0) && (warp_n == 0);

        #pragma unroll
        for (int mi = 0; mi < 2; ++mi)
            #pragma unroll
            for (int dr = 0; dr < 2; ++dr) {
                float m = -1e30f;
                #pragma unroll
                for (int ni = 0; ni < 8; ++ni)
                    m = fmaxf(m, fmaxf(sacc[mi][ni][2 * dr], sacc[mi][ni][2 * dr + 1]));
                m = fmaxf(m, __shfl_xor_sync(0xffffffffu, m, 1));
                m = fmaxf(m, __shfl_xor_sync(0xffffffffu, m, 2));
                redm[warp_n * 64 + s_wm + mi * 16 + dr * 8 + g] = m;
            }
        __syncthreads();

        #pragma unroll
        for (int mi = 0; mi < 2; ++mi)
            #pragma unroll
            for (int dr = 0; dr < 2; ++dr) {
                const int row = s_wm + mi * 16 + dr * 8 + g;
                float m1 = fmaxf(fmaxf(redm[row], redm[64 + row]),
                                 fmaxf(redm[128 + row], redm[192 + row]));
                float s1 = 0.f, s2 = 0.f;
                #pragma unroll
                for (int ni = 0; ni < 8; ++ni) {
                    float e0 = __expf(sacc[mi][ni][2 * dr] - m1);
                    float e1 = __expf(sacc[mi][ni][2 * dr + 1] - m1);
                    sacc[mi][ni][2 * dr] = e0;
                    sacc[mi][ni][2 * dr + 1] = e1;
                    s1 += e0 + e1;
                    if (bias_w) {
                        float2 d2 = *(const float2*)&Pf[row * VS_S + ni * 8 + 2 * tg];
                        s2 += e0 * __expf(d2.x) + e1 * __expf(d2.y);
                    }
                }
                if (!bias_w) s2 = s1;
                s1 += __shfl_xor_sync(0xffffffffu, s1, 1);
                s1 += __shfl_xor_sync(0xffffffffu, s1, 2);
                s2 += __shfl_xor_sync(0xffffffffu, s2, 1);
                s2 += __shfl_xor_sync(0xffffffffu, s2, 2);
                reds1[warp_n * 64 + row] = s1;
                reds2[warp_n * 64 + row] = s2;
            }
        __syncthreads();

        #pragma unroll
        for (int mi = 0; mi < 2; ++mi)
            #pragma unroll
            for (int dr = 0; dr < 2; ++dr) {
                const int row = s_wm + mi * 16 + dr * 8 + g;
                float inv1 = 1.f / (reds1[row] + reds1[64 + row] +
                                    reds1[128 + row] + reds1[192 + row]);
                float inv2 = 1.f / (reds2[row] + reds2[64 + row] +
                                    reds2[128 + row] + reds2[192 + row]);
                float* aw = awp_base + (size_t)(r0 + row) * S_LEN + s_wn + 2 * tg;
                #pragma unroll
                for (int ni = 0; ni < 8; ++ni) {
                    float e0 = sacc[mi][ni][2 * dr], e1 = sacc[mi][ni][2 * dr + 1];
                    float2 w; w.x = e0 * inv1; w.y = e1 * inv1;
                    *(float2*)(aw + ni * 8) = w;
                    float p0 = e0 * inv2, p1 = e1 * inv2;
                    if (bias_w) {
                        float2 d2 = *(const float2*)&Pf[row * VS_S + ni * 8 + 2 * tg];
                        p0 *= __expf(d2.x);
                        p1 *= __expf(d2.y);
                    }
                    uint2 pw; pw.x = t32(p0); pw.y = t32(p1);
                    *(uint2*)&Pm[row * VS_S + s_wn + ni * 8 + 2 * tg] = pw;
                }
            }
        __syncthreads();

        // ---- AV: 64x64, k=256 ----
        float vacc[2][2][4];
        #pragma unroll
        for (int mi = 0; mi < 2; ++mi)
            #pragma unroll
            for (int ni = 0; ni < 2; ++ni)
                #pragma unroll
                for (int q = 0; q < 4; ++q) vacc[mi][ni][q] = 0.f;

        #pragma unroll 8
        for (int ks = 0; ks < 32; ++ks) {
            const int kk = ks * 8 + tg;
            unsigned af[2][4], bf[2][2];
            #pragma unroll
            for (int mi = 0; mi < 2; ++mi) {
                int ar = (a_wm + mi * 16 + g) * VS_S + kk;
                af[mi][0] = Pm[ar];
                af[mi][1] = Pm[ar + 8 * VS_S];
                af[mi][2] = Pm[ar + 4];
                af[mi][3] = Pm[ar + 8 * VS_S + 4];
            }
            #pragma unroll
            for (int ni = 0; ni < 2; ++ni) {
                int br = (a_wn + ni * 8 + g) * VS_S + kk;
                bf[ni][0] = Vt[br];
                bf[ni][1] = Vt[br + 4];
            }
            #pragma unroll
            for (int mi = 0; mi < 2; ++mi)
                #pragma unroll
                for (int ni = 0; ni < 2; ++ni)
                    mma8(vacc[mi][ni], af[mi], bf[ni]);
        }

        #pragma unroll
        for (int mi = 0; mi < 2; ++mi)
            #pragma unroll
            for (int dr = 0; dr < 2; ++dr) {
                const int row = a_wm + mi * 16 + dr * 8 + g;
                const int s = r0 + row;
                const int sp = ((b & 15) << 4) | (s >> 4);
                #pragma unroll
                for (int ni = 0; ni < 2; ++ni) {
                    const int c0 = ((s & 15) << 6) | (a_wn + ni * 8 + 2 * tg);
                    float2 o;
                    o.x = vacc[mi][ni][2 * dr];
                    o.y = vacc[mi][ni][2 * dr + 1];
                    *(float2*)&attnb[((size_t)bp * S_LEN + sp) * D + c0] = o;
                }
            }
        __syncthreads();
    }
}

// ---------------- mean over heads ----------------
__global__ void awmean_kernel(const float* __restrict__ awp, float* __restrict__ out) {
    int idx = blockIdx.x * blockDim.x + threadIdx.x;
    int b = idx >> 16;
    int r = idx & 65535;
    const float* p = awp + (size_t)b * NH * 65536 + r;
    float sum = 0.f;
    #pragma unroll
    for (int h = 0; h < NH; ++h) sum += p[(size_t)h * 65536];
    out[idx] = sum * (1.f / NH);
}

// ---------------- residual + layernorm ----------------
__global__ void __launch_bounds__(256) ln_kernel(const float* __restrict__ Y,
                                                 const float* __restrict__ X,
                                                 const float* __restrict__ G,
                                                 const float* __restrict__ Bb,
                                                 float* __restrict__ out) {
    __shared__ float red[8];
    const int row = blockIdx.x, tid = threadIdx.x;
    const int lane = tid & 31, w = tid >> 5;
    const size_t off = (size_t)row * D + tid * 4;
    float4 v  = *(const float4*)(Y + off);
    float4 xx = *(const float4*)(X + off);
    v.x += xx.x; v.y += xx.y; v.z += xx.z; v.w += xx.w;

    float s = v.x + v.y + v.z + v.w;
    #pragma unroll
    for (int o = 16; o; o >>= 1) s += __shfl_xor_sync(0xffffffffu, s, o);
    if (lane == 0) red[w] = s;
    __syncthreads();
    float tot = 0.f;
    #pragma unroll
    for (int i = 0; i < 8; ++i) tot += red[i];
    float mu = tot * (1.f / 1024.f);
    __syncthreads();

    float d0 = v.x - mu, d1 = v.y - mu, d2 = v.z - mu, d3 = v.w - mu;
    float sq = d0 * d0 + d1 * d1 + d2 * d2 + d3 * d3;
    #pragma unroll
    for (int o = 16; o; o >>= 1) sq += __shfl_xor_sync(0xffffffffu, sq, o);
    if (lane == 0) red[w] = sq;
    __syncthreads();
    float vtot = 0.f;
    #pragma unroll
    for (int i = 0; i < 8; ++i) vtot += red[i];
    float rstd = rsqrtf(vtot * (1.f / 1024.f) + 1e-5f);

    float4 g4 = *(const float4*)(G  + tid * 4);
    float4 b4 = *(const float4*)(Bb + tid * 4);
    float4 o;
    o.x = d0 * rstd * g4.x + b4.x;
    o.y = d1 * rstd * g4.y + b4.y;
    o.z = d2 * rstd * g4.z + b4.z;
    o.w = d3 * rstd * g4.w + b4.w;
    *(float4*)(out + off) = o;
}

// ---------------- launcher ----------------
extern "C" void kernel_launch(void* const* d_in, const int* in_sizes, int n_in,
                              void* d_out, int out_size) {
    const float* x   = (const float*)d_in[0];
    const float* pf  = (const float*)d_in[1];
    const float* wq  = (const float*)d_in[2];
    const float* bq  = (const float*)d_in[3];
    const float* wk  = (const float*)d_in[4];
    const float* bk  = (const float*)d_in[5];
    const float* wv  = (const float*)d_in[6];
    const float* bv  = (const float*)d_in[7];
    const float* wo  = (const float*)d_in[8];
    const float* bo  = (const float*)d_in[9];
    const float* lng = (const float*)d_in[10];
    const float* lnb = (const float*)d_in[11];

    float* out    = (float*)d_out;
    float* out_aw = out + (size_t)M_ROWS * D;

    float *qp, *kp, *vp, *ap, *yp, *awpp, *divp;
    cudaGetSymbolAddress((void**)&qp,   g_q);
    cudaGetSymbolAddress((void**)&kp,   g_k);
    cudaGetSymbolAddress((void**)&vp,   g_v);
    cudaGetSymbolAddress((void**)&ap,   g_attn);
    cudaGetSymbolAddress((void**)&yp,   g_y);
    cudaGetSymbolAddress((void**)&awpp, g_awp);
    cudaGetSymbolAddress((void**)&divp, g_div);

    div_kernel<<<BATCH, 64>>>(pf, divp);

    const int GEMM_SMEM = 4 * TILE_W * 4;
    cudaFuncSetAttribute(gemm_tf32, cudaFuncAttributeMaxDynamicSharedMemorySize,
                         GEMM_SMEM);

    dim3 gg(D / 128, M_ROWS / 128);
    gemm_tf32<<<gg, 256, GEMM_SMEM>>>(x, wq, bq, qp, 0.125f, 0);
    gemm_tf32<<<gg, 256, GEMM_SMEM>>>(x, wk, bk, kp, 1.0f, 0);
    gemm_tf32<<<gg, 256, GEMM_SMEM>>>(x, wv, bv, vp, 1.0f, 0);

    const int ATTN_SMEM =
        (256 * KS_S + 64 * VS_S + 64 * KS_S + 64 * VS_S + 768) * 4;  // 223232 B
    cudaFuncSetAttribute(attn_tc, cudaFuncAttributeMaxDynamicSharedMemorySize,
                         ATTN_SMEM);
    attn_tc<<<BATCH * NH, 256, ATTN_SMEM>>>(qp, kp, vp, divp, ap, awpp);

    awmean_kernel<<<(BATCH * S_LEN * S_LEN) / 1024, 1024>>>(awpp, out_aw);

    gemm_tf32<<<gg, 256, GEMM_SMEM>>>(ap, wo, bo, yp, 1.0f, 1);
    ln_kernel<<<M_ROWS, 256>>>(yp, x, lng, lnb, out);
}

// round 5
// speedup vs baseline: 4.8473x; 1.2156x over previous
#include <cuda_runtime.h>

#define M_ROWS 8192   // B*S
#define D      1024
#define S_LEN  256
#define NH     16
#define DK     64
#define BATCH  32

#define BSMS   20     // bf16 gemm smem row stride (uint32 words: 16 data + 4 pad)
#define BTILE_W (128 * BSMS)

#define KS_S   68     // K/Q smem row stride (words), ≡4 mod 32
#define VS_S   260    // Vt/P smem row stride (words), ≡4 mod 32

// ---------------- scratch ----------------
__device__ float g_q[M_ROWS * D];
__device__ float g_k[M_ROWS * D];
__device__ float g_v[M_ROWS * D];
__device__ float g_attn[M_ROWS * D];
__device__ float g_y[M_ROWS * D];
__device__ float g_awp[(size_t)BATCH * NH * S_LEN * S_LEN];
__device__ float g_div[BATCH * 64 * 64];

// ---------------- helpers ----------------
__device__ __forceinline__ unsigned t32(float f) {
    unsigned u; asm("cvt.rna.tf32.f32 %0,%1;" : "=r"(u) : "f"(f)); return u;
}
__device__ __forceinline__ uint4 t32x4(float4 v) {
    uint4 u; u.x = t32(v.x); u.y = t32(v.y); u.z = t32(v.z); u.w = t32(v.w); return u;
}
__device__ __forceinline__ unsigned bpack(float lo, float hi) {
    unsigned u; asm("cvt.rn.bf16x2.f32 %0,%1,%2;" : "=r"(u) : "f"(hi), "f"(lo));
    return u;
}
__device__ __forceinline__ void mma8(float* c, const unsigned* a, const unsigned* b) {
    asm("mma.sync.aligned.m16n8k8.row.col.f32.tf32.tf32.f32 "
        "{%0,%1,%2,%3},{%4,%5,%6,%7},{%8,%9},{%0,%1,%2,%3};"
        : "+f"(c[0]), "+f"(c[1]), "+f"(c[2]), "+f"(c[3])
        : "r"(a[0]), "r"(a[1]), "r"(a[2]), "r"(a[3]), "r"(b[0]), "r"(b[1]));
}
__device__ __forceinline__ void mma16b(float* c, const unsigned* a, const unsigned* b) {
    asm("mma.sync.aligned.m16n8k16.row.col.f32.bf16.bf16.f32 "
        "{%0,%1,%2,%3},{%4,%5,%6,%7},{%8,%9},{%0,%1,%2,%3};"
        : "+f"(c[0]), "+f"(c[1]), "+f"(c[2]), "+f"(c[3])
        : "r"(a[0]), "r"(a[1]), "r"(a[2]), "r"(a[3]), "r"(b[0]), "r"(b[1]));
}

// ---------------- div bias ----------------
__global__ void div_kernel(const float* __restrict__ pf, float* __restrict__ divb) {
    __shared__ float p[64 * 129];
    const int b = blockIdx.x;
    const int tid = threadIdx.x;  // 64 threads
    for (int idx = tid; idx < 64 * 128; idx += 64) {
        int r = idx >> 7, f = idx & 127;
        p[r * 129 + f] = pf[(size_t)b * 64 * 128 + idx];
    }
    __syncthreads();
    float simr[64];
    float mx = -1e30f;
    for (int q = 0; q < 64; ++q) {
        float dsum = 0.f;
        #pragma unroll 8
        for (int f = 0; f < 128; ++f)
            dsum = fmaf(p[tid * 129 + f], p[q * 129 + f], dsum);
        simr[q] = dsum;
        mx = fmaxf(mx, dsum);
    }
    float sum = 0.f;
    for (int q = 0; q < 64; ++q) { simr[q] = __expf(simr[q] - mx); sum += simr[q]; }
    float inv = 1.f / sum;
    for (int q = 0; q < 64; ++q)
        divb[((size_t)b * 64 + tid) * 64 + q] = 1.f - simr[q] * inv;
}

// ---------------- BF16 tensor-core GEMM: C[m,n] = sum_k A[m,k]*W[n,k] ----------------
__global__ void __launch_bounds__(256) gemm_bf16(const float* __restrict__ A,
                                                 const float* __restrict__ W,
                                                 const float* __restrict__ bias,
                                                 float* __restrict__ C,
                                                 float scale, int epi) {
    extern __shared__ unsigned smu[];
    unsigned* AsB = smu;                 // 2 buffers x 128 x BSMS (bf16x2 words)
    unsigned* BsB = smu + 2 * BTILE_W;

    const int tid = threadIdx.x;
    const int m0 = blockIdx.y * 128, n0 = blockIdx.x * 128;
    const int lr = tid >> 3, lwc = (tid & 7) * 2;   // word col (bf16x2)
    const float* Ap = A + (size_t)(m0 + lr) * D + (tid & 7) * 4;
    const float* Wp = W + (size_t)(n0 + lr) * D + (tid & 7) * 4;

    const int wid = tid >> 5, lane = tid & 31;
    const int g = lane >> 2, tg = lane & 3;
    const int wm = (wid & 3) * 32, wn = (wid >> 2) * 64;

    float acc[2][8][4];
    #pragma unroll
    for (int mi = 0; mi < 2; ++mi)
        #pragma unroll
        for (int ni = 0; ni < 8; ++ni)
            #pragma unroll
            for (int q = 0; q < 4; ++q) acc[mi][ni][q] = 0.f;

    // stage k-tile 0
    #pragma unroll
    for (int p = 0; p < 4; ++p) {
        float4 a4 = *(const float4*)(Ap + (size_t)p * 32 * D);
        float4 w4 = *(const float4*)(Wp + (size_t)p * 32 * D);
        uint2 au; au.x = bpack(a4.x, a4.y); au.y = bpack(a4.z, a4.w);
        uint2 wu; wu.x = bpack(w4.x, w4.y); wu.y = bpack(w4.z, w4.w);
        *(uint2*)&AsB[(lr + 32 * p) * BSMS + lwc] = au;
        *(uint2*)&BsB[(lr + 32 * p) * BSMS + lwc] = wu;
    }
    __syncthreads();

    for (int kt = 0; kt < 32; ++kt) {
        const int cur = (kt & 1) * BTILE_W, nxt = ((kt + 1) & 1) * BTILE_W;
        float4 pa[4], pw[4];
        if (kt < 31) {
            #pragma unroll
            for (int p = 0; p < 4; ++p) {
                pa[p] = *(const float4*)(Ap + (size_t)p * 32 * D + (kt + 1) * 32);
                pw[p] = *(const float4*)(Wp + (size_t)p * 32 * D + (kt + 1) * 32);
            }
        }
        const unsigned* Ac = AsB + cur;
        const unsigned* Bc = BsB + cur;
        #pragma unroll
        for (int ks = 0; ks < 2; ++ks) {          // two k16 steps cover k=32
            const int kk = ks * 8 + tg;
            unsigned af[2][4], bf[8][2];
            #pragma unroll
            for (int mi = 0; mi < 2; ++mi) {
                int base = (wm + mi * 16 + g) * BSMS + kk;
                af[mi][0] = Ac[base];
                af[mi][1] = Ac[base + 8 * BSMS];
                af[mi][2] = Ac[base + 4];
                af[mi][3] = Ac[base + 8 * BSMS + 4];
            }
            #pragma unroll
            for (int ni = 0; ni < 8; ++ni) {
                int base = (wn + ni * 8 + g) * BSMS + kk;
                bf[ni][0] = Bc[base];
                bf[ni][1] = Bc[base + 4];
            }
            #pragma unroll
            for (int mi = 0; mi < 2; ++mi)
                #pragma unroll
                for (int ni = 0; ni < 8; ++ni)
                    mma16b(acc[mi][ni], af[mi], bf[ni]);
        }
        if (kt < 31) {
            #pragma unroll
            for (int p = 0; p < 4; ++p) {
                uint2 au; au.x = bpack(pa[p].x, pa[p].y); au.y = bpack(pa[p].z, pa[p].w);
                uint2 wu; wu.x = bpack(pw[p].x, pw[p].y); wu.y = bpack(pw[p].z, pw[p].w);
                *(uint2*)&AsB[nxt + (lr + 32 * p) * BSMS + lwc] = au;
                *(uint2*)&BsB[nxt + (lr + 32 * p) * BSMS + lwc] = wu;
            }
        }
        __syncthreads();
    }

    // epilogue (fragment layout identical to k8 case)
    float2 bfr[8];
    #pragma unroll
    for (int ni = 0; ni < 8; ++ni)
        bfr[ni] = *(const float2*)&bias[n0 + wn + ni * 8 + 2 * tg];

    if (epi == 0) {
        #pragma unroll
        for (int mi = 0; mi < 2; ++mi) {
            const int mbase = m0 + wm + mi * 16 + g;
            #pragma unroll
            for (int r = 0; r < 2; ++r) {
                int m = mbase + r * 8;
                int b_ = m >> 8, s = m & 255;
                #pragma unroll
                for (int ni = 0; ni < 8; ++ni) {
                    int n = n0 + wn + ni * 8 + 2 * tg;
                    int h = n >> 6, kk = n & 63;
                    float2 o;
                    o.x = (acc[mi][ni][2 * r + 0] + bfr[ni].x) * scale;
                    o.y = (acc[mi][ni][2 * r + 1] + bfr[ni].y) * scale;
                    *(float2*)&C[(((size_t)(b_ * NH + h) * S_LEN + s) << 6) + kk] = o;
                }
            }
        }
    } else {
        #pragma unroll
        for (int mi = 0; mi < 2; ++mi) {
            const int mbase = m0 + wm + mi * 16 + g;
            #pragma unroll
            for (int r = 0; r < 2; ++r) {
                int m = mbase + r * 8;
                #pragma unroll
                for (int ni = 0; ni < 8; ++ni) {
                    int n = n0 + wn + ni * 8 + 2 * tg;
                    float2 o;
                    o.x = acc[mi][ni][2 * r + 0] + bfr[ni].x;
                    o.y = acc[mi][ni][2 * r + 1] + bfr[ni].y;
                    *(float2*)&C[(size_t)m * D + n] = o;
                }
            }
        }
    }
}

// ---------------- tensor-core fused attention per (b, head) ----------------
__global__ void __launch_bounds__(256) attn_tc(const float* __restrict__ Q,
                                               const float* __restrict__ K,
                                               const float* __restrict__ V,
                                               const float* __restrict__ Div,
                                               float* __restrict__ attnb,
                                               float* __restrict__ awp) {
    extern __shared__ unsigned smu[];
    unsigned* Ks = smu;                      // [256][KS_S]
    unsigned* Vt = Ks + 256 * KS_S;          // [64][VS_S]  (V transposed: [dk][s])
    unsigned* Qs = Vt + 64 * VS_S;           // [64][KS_S]
    unsigned* Pm = Qs + 64 * KS_S;           // [64][VS_S]  (tf32 P / fp32 bias stage)
    float* red = (float*)(Pm + 64 * VS_S);   // [3][4][64]

    const int tid = threadIdx.x;
    const int bh = blockIdx.x, b = bh >> 4, n = bh & 15;
    const size_t base = (size_t)bh * (S_LEN * DK);

    {
        const float4* K4 = (const float4*)(K + base);
        const float4* V4 = (const float4*)(V + base);
        for (int idx4 = tid; idx4 < 4096; idx4 += 256) {
            int r = idx4 >> 4, c4 = (idx4 & 15) << 2;
            *(uint4*)&Ks[r * KS_S + c4] = t32x4(K4[idx4]);
            float4 v = V4[idx4];
            Vt[(c4 + 0) * VS_S + r] = t32(v.x);
            Vt[(c4 + 1) * VS_S + r] = t32(v.y);
            Vt[(c4 + 2) * VS_S + r] = t32(v.z);
            Vt[(c4 + 3) * VS_S + r] = t32(v.w);
        }
        float* Pf = (float*)Pm;
        for (int idx = tid; idx < 4096; idx += 256) {
            int r = idx >> 6, c = idx & 63;
            Pf[r * VS_S + c] = 0.1f * Div[(((b << 6) + r) << 6) + c];
        }
    }

    const int lane = tid & 31, wid = tid >> 5;
    const int g = lane >> 2, tg = lane & 3;
    const int s_wm = (wid & 1) * 32;
    const int warp_n = wid >> 1;
    const int s_wn = warp_n * 64;
    const int a_wm = (wid & 1) * 32;
    const int a_wn = (wid >> 1) * 16;

    float* awp_base = awp + (size_t)bh * (S_LEN * S_LEN);
    float* Pf = (float*)Pm;
    float* redm  = red;
    float* reds1 = red + 256;
    float* reds2 = red + 512;
    const int bp = 2 * n + (b >> 4);

    for (int t = 0; t < 4; ++t) {
        const int r0 = t << 6;
        {
            const float4* Q4 = (const float4*)(Q + base + ((size_t)r0 << 6));
            for (int idx4 = tid; idx4 < 1024; idx4 += 256) {
                int r = idx4 >> 4, c4 = (idx4 & 15) << 2;
                *(uint4*)&Qs[r * KS_S + c4] = t32x4(Q4[idx4]);
            }
        }
        __syncthreads();

        float sacc[2][8][4];
        #pragma unroll
        for (int mi = 0; mi < 2; ++mi)
            #pragma unroll
            for (int ni = 0; ni < 8; ++ni)
                #pragma unroll
                for (int q = 0; q < 4; ++q) sacc[mi][ni][q] = 0.f;

        #pragma unroll
        for (int ks = 0; ks < 8; ++ks) {
            const int kk = ks * 8 + tg;
            unsigned af[2][4], bf[8][2];
            #pragma unroll
            for (int mi = 0; mi < 2; ++mi) {
                int ar = (s_wm + mi * 16 + g) * KS_S + kk;
                af[mi][0] = Qs[ar];
                af[mi][1] = Qs[ar + 8 * KS_S];
                af[mi][2] = Qs[ar + 4];
                af[mi][3] = Qs[ar + 8 * KS_S + 4];
            }
            #pragma unroll
            for (int ni = 0; ni < 8; ++ni) {
                int br = (s_wn + ni * 8 + g) * KS_S + kk;
                bf[ni][0] = Ks[br];
                bf[ni][1] = Ks[br + 4];
            }
            #pragma unroll
            for (int mi = 0; mi < 2; ++mi)
                #pragma unroll
                for (int ni = 0; ni < 8; ++ni)
                    mma8(sacc[mi][ni], af[mi], bf[ni]);
        }

        const bool bias_w = (t == 0) && (warp_n == 0);

        #pragma unroll
        for (int mi = 0; mi < 2; ++mi)
            #pragma unroll
            for (int dr = 0; dr < 2; ++dr) {
                float m = -1e30f;
                #pragma unroll
                for (int ni = 0; ni < 8; ++ni)
                    m = fmaxf(m, fmaxf(sacc[mi][ni][2 * dr], sacc[mi][ni][2 * dr + 1]));
                m = fmaxf(m, __shfl_xor_sync(0xffffffffu, m, 1));
                m = fmaxf(m, __shfl_xor_sync(0xffffffffu, m, 2));
                redm[warp_n * 64 + s_wm + mi * 16 + dr * 8 + g] = m;
            }
        __syncthreads();

        #pragma unroll
        for (int mi = 0; mi < 2; ++mi)
            #pragma unroll
            for (int dr = 0; dr < 2; ++dr) {
                const int row = s_wm + mi * 16 + dr * 8 + g;
                float m1 = fmaxf(fmaxf(redm[row], redm[64 + row]),
                                 fmaxf(redm[128 + row], redm[192 + row]));
                float s1 = 0.f, s2 = 0.f;
                #pragma unroll
                for (int ni = 0; ni < 8; ++ni) {
                    float e0 = __expf(sacc[mi][ni][2 * dr] - m1);
                    float e1 = __expf(sacc[mi][ni][2 * dr + 1] - m1);
                    sacc[mi][ni][2 * dr] = e0;
                    sacc[mi][ni][2 * dr + 1] = e1;
                    s1 += e0 + e1;
                    if (bias_w) {
                        float2 d2 = *(const float2*)&Pf[row * VS_S + ni * 8 + 2 * tg];
                        s2 += e0 * __expf(d2.x) + e1 * __expf(d2.y);
                    }
                }
                if (!bias_w) s2 = s1;
                s1 += __shfl_xor_sync(0xffffffffu, s1, 1);
                s1 += __shfl_xor_sync(0xffffffffu, s1, 2);
                s2 += __shfl_xor_sync(0xffffffffu, s2, 1);
                s2 += __shfl_xor_sync(0xffffffffu, s2, 2);
                reds1[warp_n * 64 + row] = s1;
                reds2[warp_n * 64 + row] = s2;
            }
        __syncthreads();

        #pragma unroll
        for (int mi = 0; mi < 2; ++mi)
            #pragma unroll
            for (int dr = 0; dr < 2; ++dr) {
                const int row = s_wm + mi * 16 + dr * 8 + g;
                float inv1 = 1.f / (reds1[row] + reds1[64 + row] +
                                    reds1[128 + row] + reds1[192 + row]);
                float inv2 = 1.f / (reds2[row] + reds2[64 + row] +
                                    reds2[128 + row] + reds2[192 + row]);
                float* aw = awp_base + (size_t)(r0 + row) * S_LEN + s_wn + 2 * tg;
                #pragma unroll
                for (int ni = 0; ni < 8; ++ni) {
                    float e0 = sacc[mi][ni][2 * dr], e1 = sacc[mi][ni][2 * dr + 1];
                    float2 w; w.x = e0 * inv1; w.y = e1 * inv1;
                    *(float2*)(aw + ni * 8) = w;
                    float p0 = e0 * inv2, p1 = e1 * inv2;
                    if (bias_w) {
                        float2 d2 = *(const float2*)&Pf[row * VS_S + ni * 8 + 2 * tg];
                        p0 *= __expf(d2.x);
                        p1 *= __expf(d2.y);
                    }
                    uint2 pw; pw.x = t32(p0); pw.y = t32(p1);
                    *(uint2*)&Pm[row * VS_S + s_wn + ni * 8 + 2 * tg] = pw;
                }
            }
        __syncthreads();

        float vacc[2][2][4];
        #pragma unroll
        for (int mi = 0; mi < 2; ++mi)
            #pragma unroll
            for (int ni = 0; ni < 2; ++ni)
                #pragma unroll
                for (int q = 0; q < 4; ++q) vacc[mi][ni][q] = 0.f;

        #pragma unroll 8
        for (int ks = 0; ks < 32; ++ks) {
            const int kk = ks * 8 + tg;
            unsigned af[2][4], bf[2][2];
            #pragma unroll
            for (int mi = 0; mi < 2; ++mi) {
                int ar = (a_wm + mi * 16 + g) * VS_S + kk;
                af[mi][0] = Pm[ar];
                af[mi][1] = Pm[ar + 8 * VS_S];
                af[mi][2] = Pm[ar + 4];
                af[mi][3] = Pm[ar + 8 * VS_S + 4];
            }
            #pragma unroll
            for (int ni = 0; ni < 2; ++ni) {
                int br = (a_wn + ni * 8 + g) * VS_S + kk;
                bf[ni][0] = Vt[br];
                bf[ni][1] = Vt[br + 4];
            }
            #pragma unroll
            for (int mi = 0; mi < 2; ++mi)
                #pragma unroll
                for (int ni = 0; ni < 2; ++ni)
                    mma8(vacc[mi][ni], af[mi], bf[ni]);
        }

        #pragma unroll
        for (int mi = 0; mi < 2; ++mi)
            #pragma unroll
            for (int dr = 0; dr < 2; ++dr) {
                const int row = a_wm + mi * 16 + dr * 8 + g;
                const int s = r0 + row;
                const int sp = ((b & 15) << 4) | (s >> 4);
                #pragma unroll
                for (int ni = 0; ni < 2; ++ni) {
                    const int c0 = ((s & 15) << 6) | (a_wn + ni * 8 + 2 * tg);
                    float2 o;
                    o.x = vacc[mi][ni][2 * dr];
                    o.y = vacc[mi][ni][2 * dr + 1];
                    *(float2*)&attnb[((size_t)bp * S_LEN + sp) * D + c0] = o;
                }
            }
        __syncthreads();
    }
}

// ---------------- mean over heads (vectorized) ----------------
__global__ void awmean_kernel(const float* __restrict__ awp, float* __restrict__ out) {
    int idx = blockIdx.x * blockDim.x + threadIdx.x;   // float4 index, < 32*16384
    int b = idx >> 14;
    int r = (idx & 16383) << 2;
    const float* p = awp + (size_t)b * NH * 65536 + r;
    float4 sum = *(const float4*)p;
    #pragma unroll
    for (int h = 1; h < NH; ++h) {
        float4 v = *(const float4*)(p + (size_t)h * 65536);
        sum.x += v.x; sum.y += v.y; sum.z += v.z; sum.w += v.w;
    }
    sum.x *= (1.f / NH); sum.y *= (1.f / NH);
    sum.z *= (1.f / NH); sum.w *= (1.f / NH);
    *(float4*)&out[((size_t)b << 16) + r] = sum;
}

// ---------------- residual + layernorm ----------------
__global__ void __launch_bounds__(256) ln_kernel(const float* __restrict__ Y,
                                                 const float* __restrict__ X,
                                                 const float* __restrict__ G,
                                                 const float* __restrict__ Bb,
                                                 float* __restrict__ out) {
    __shared__ float red[8];
    const int row = blockIdx.x, tid = threadIdx.x;
    const int lane = tid & 31, w = tid >> 5;
    const size_t off = (size_t)row * D + tid * 4;
    float4 v  = *(const float4*)(Y + off);
    float4 xx = *(const float4*)(X + off);
    v.x += xx.x; v.y += xx.y; v.z += xx.z; v.w += xx.w;

    float s = v.x + v.y + v.z + v.w;
    #pragma unroll
    for (int o = 16; o; o >>= 1) s += __shfl_xor_sync(0xffffffffu, s, o);
    if (lane == 0) red[w] = s;
    __syncthreads();
    float tot = 0.f;
    #pragma unroll
    for (int i = 0; i < 8; ++i) tot += red[i];
    float mu = tot * (1.f / 1024.f);
    __syncthreads();

    float d0 = v.x - mu, d1 = v.y - mu, d2 = v.z - mu, d3 = v.w - mu;
    float sq = d0 * d0 + d1 * d1 + d2 * d2 + d3 * d3;
    #pragma unroll
    for (int o = 16; o; o >>= 1) sq += __shfl_xor_sync(0xffffffffu, sq, o);
    if (lane == 0) red[w] = sq;
    __syncthreads();
    float vtot = 0.f;
    #pragma unroll
    for (int i = 0; i < 8; ++i) vtot += red[i];
    float rstd = rsqrtf(vtot * (1.f / 1024.f) + 1e-5f);

    float4 g4 = *(const float4*)(G  + tid * 4);
    float4 b4 = *(const float4*)(Bb + tid * 4);
    float4 o;
    o.x = d0 * rstd * g4.x + b4.x;
    o.y = d1 * rstd * g4.y + b4.y;
    o.z = d2 * rstd * g4.z + b4.z;
    o.w = d3 * rstd * g4.w + b4.w;
    *(float4*)(out + off) = o;
}

// ---------------- launcher ----------------
extern "C" void kernel_launch(void* const* d_in, const int* in_sizes, int n_in,
                              void* d_out, int out_size) {
    const float* x   = (const float*)d_in[0];
    const float* pf  = (const float*)d_in[1];
    const float* wq  = (const float*)d_in[2];
    const float* bq  = (const float*)d_in[3];
    const float* wk  = (const float*)d_in[4];
    const float* bk  = (const float*)d_in[5];
    const float* wv  = (const float*)d_in[6];
    const float* bv  = (const float*)d_in[7];
    const float* wo  = (const float*)d_in[8];
    const float* bo  = (const float*)d_in[9];
    const float* lng = (const float*)d_in[10];
    const float* lnb = (const float*)d_in[11];

    float* out    = (float*)d_out;
    float* out_aw = out + (size_t)M_ROWS * D;

    float *qp, *kp, *vp, *ap, *yp, *awpp, *divp;
    cudaGetSymbolAddress((void**)&qp,   g_q);
    cudaGetSymbolAddress((void**)&kp,   g_k);
    cudaGetSymbolAddress((void**)&vp,   g_v);
    cudaGetSymbolAddress((void**)&ap,   g_attn);
    cudaGetSymbolAddress((void**)&yp,   g_y);
    cudaGetSymbolAddress((void**)&awpp, g_awp);
    cudaGetSymbolAddress((void**)&divp, g_div);

    div_kernel<<<BATCH, 64>>>(pf, divp);

    const int GEMM_SMEM = 4 * BTILE_W * 4;   // 40960 bytes -> 2 CTAs/SM
    cudaFuncSetAttribute(gemm_bf16, cudaFuncAttributeMaxDynamicSharedMemorySize,
                         GEMM_SMEM);

    dim3 gg(D / 128, M_ROWS / 128);
    gemm_bf16<<<gg, 256, GEMM_SMEM>>>(x, wq, bq, qp, 0.125f, 0);
    gemm_bf16<<<gg, 256, GEMM_SMEM>>>(x, wk, bk, kp, 1.0f, 0);
    gemm_bf16<<<gg, 256, GEMM_SMEM>>>(x, wv, bv, vp, 1.0f, 0);

    const int ATTN_SMEM =
        (256 * KS_S + 64 * VS_S + 64 * KS_S + 64 * VS_S + 768) * 4;
    cudaFuncSetAttribute(attn_tc, cudaFuncAttributeMaxDynamicSharedMemorySize,
                         ATTN_SMEM);
    attn_tc<<<BATCH * NH, 256, ATTN_SMEM>>>(qp, kp, vp, divp, ap, awpp);

    awmean_kernel<<<(BATCH * S_LEN * S_LEN / 4) / 256, 256>>>(awpp, out_aw);

    gemm_bf16<<<gg, 256, GEMM_SMEM>>>(ap, wo, bo, yp, 1.0f, 1);
    ln_kernel<<<M_ROWS, 256>>>(yp, x, lng, lnb, out);
}